// round 3
// baseline (speedup 1.0000x reference)
#include <cuda_runtime.h>
#include <cuda_bf16.h>
#include <math.h>

// Problem constants
#define Bn 8192
#define Tn 40
#define En 64
// derived
#define ROWS (Bn*Tn)          // 327680
#define XP_SMEM  ((12288 + 64*65)*4)            // 65792 B
#define GRU_SMEM ((12288 + 64*68)*4)            // 66560 B
#define MLP_SMEM ((16384+8192+64+128+64+16+8*256)*4)  // 107584 B

// -------- device scratch (no allocations allowed) --------
__device__ float g_xproj[(size_t)ROWS * 192];   // 240 MB
__device__ int   g_maskMode;                    // 0=u8, 1=int32, 2=float32
__device__ float g_partials[2048];              // [0..1023] loss, [1024..2047] count

__device__ __forceinline__ float mval(const void* m, int idx, int mode) {
    if (mode == 1) return ((const int*)m)[idx] ? 1.0f : 0.0f;
    if (mode == 2) return ((const float*)m)[idx];
    return ((const unsigned char*)m)[idx] ? 1.0f : 0.0f;
}
__device__ __forceinline__ float sigf(float v) { return 1.0f / (1.0f + __expf(-v)); }
__device__ __forceinline__ float tanhf_(float v) {
    // 1 - 2/(e^{2v}+1): saturates correctly at +/-1 without NaN
    return 1.0f - 2.0f / (__expf(2.0f * v) + 1.0f);
}

// -------- mask dtype probe --------
// Reads 2560 int32 words (10240 B), within the smallest candidate buffer
// (u8: 327680 B). int32 bool -> all words in {0,1}. f32 bool -> words in
// {0, 0x3F800000}. u8 packed bools produce words like 0x0101 -> neither.
__global__ void detect_k(const int* __restrict__ m32) {
    __shared__ int sB, sF;
    if (threadIdx.x == 0) { sB = 1; sF = 1; }
    __syncthreads();
    int okB = 1, okF = 1;
    for (int i = threadIdx.x; i < 2560; i += blockDim.x) {
        int v = m32[i];
        okB = okB && (v == 0 || v == 1);
        okF = okF && (v == 0 || v == 0x3F800000);
    }
    atomicAnd(&sB, okB);
    atomicAnd(&sF, okF);
    __syncthreads();
    if (threadIdx.x == 0) g_maskMode = sB ? 1 : (sF ? 2 : 0);
}

// -------- xproj = x @ W + bi  (M=327680, K=64, N=192) --------
// 1280 CTAs x 4 tiles x 64 rows. Thread tile: 4 rows x (4 cols in each of
// the 3 gate sections). Per k: 4 scalar + 3 float4 LDS for 48 FMA.
__global__ void __launch_bounds__(256, 1) xproj_k(
    const float* __restrict__ x, const float* __restrict__ W,
    const float* __restrict__ bias)
{
    extern __shared__ float sm[];
    float* Ws = sm;            // 64*192
    float* Xs = sm + 12288;    // 64*65

    const int tid = threadIdx.x;
    for (int i = tid; i < 3072; i += 256)
        ((float4*)Ws)[i] = ((const float4*)W)[i];

    const int tx = tid & 15, ty = tid >> 4;
    const float4 ba = *(const float4*)&bias[4 * tx];
    const float4 bb = *(const float4*)&bias[64 + 4 * tx];
    const float4 bc = *(const float4*)&bias[128 + 4 * tx];

    for (int tile = 0; tile < 4; ++tile) {
        const int r0 = (blockIdx.x * 4 + tile) * 64;
        __syncthreads();
        for (int i = tid; i < 4096; i += 256) {
            int rr = i >> 6, kk = i & 63;
            Xs[rr * 65 + kk] = x[(r0 + rr) * 64 + kk];
        }
        __syncthreads();

        float az[4][4] = {}, ar_[4][4] = {}, ah[4][4] = {};
        #pragma unroll 8
        for (int k = 0; k < 64; ++k) {
            float hv[4];
            #pragma unroll
            for (int i = 0; i < 4; ++i) hv[i] = Xs[(4 * ty + i) * 65 + k];
            const float4 uz4 = *(const float4*)&Ws[k * 192 + 4 * tx];
            const float4 ur4 = *(const float4*)&Ws[k * 192 + 64 + 4 * tx];
            const float4 uh4 = *(const float4*)&Ws[k * 192 + 128 + 4 * tx];
            const float uz[4] = {uz4.x, uz4.y, uz4.z, uz4.w};
            const float ur[4] = {ur4.x, ur4.y, ur4.z, ur4.w};
            const float uh[4] = {uh4.x, uh4.y, uh4.z, uh4.w};
            #pragma unroll
            for (int i = 0; i < 4; ++i)
                #pragma unroll
                for (int j = 0; j < 4; ++j) {
                    az[i][j] += hv[i] * uz[j];
                    ar_[i][j] += hv[i] * ur[j];
                    ah[i][j] += hv[i] * uh[j];
                }
        }
        const float bav[4] = {ba.x, ba.y, ba.z, ba.w};
        const float bbv[4] = {bb.x, bb.y, bb.z, bb.w};
        const float bcv[4] = {bc.x, bc.y, bc.z, bc.w};
        #pragma unroll
        for (int i = 0; i < 4; ++i) {
            const size_t base = (size_t)(r0 + 4 * ty + i) * 192;
            float4 o;
            o.x = az[i][0] + bav[0]; o.y = az[i][1] + bav[1];
            o.z = az[i][2] + bav[2]; o.w = az[i][3] + bav[3];
            *(float4*)&g_xproj[base + 4 * tx] = o;
            o.x = ar_[i][0] + bbv[0]; o.y = ar_[i][1] + bbv[1];
            o.z = ar_[i][2] + bbv[2]; o.w = ar_[i][3] + bbv[3];
            *(float4*)&g_xproj[base + 64 + 4 * tx] = o;
            o.x = ah[i][0] + bcv[0]; o.y = ah[i][1] + bcv[1];
            o.z = ah[i][2] + bcv[2]; o.w = ah[i][3] + bcv[3];
            *(float4*)&g_xproj[base + 128 + 4 * tx] = o;
        }
    }
}

// -------- GRU recurrence: 128 CTAs x 64 batch rows, persistent over T --------
// Per step: rp = H @ U (64x64x192) with thread tile 4 rows x 4 j-triples,
// then thread-local gate math (its cols are {j, 64+j, 128+j}).
__global__ void __launch_bounds__(256, 1) gru_k(
    const void* __restrict__ mask, const float* __restrict__ U,
    const float* __restrict__ bias, float* __restrict__ y)
{
    extern __shared__ float sm[];
    float* Us = sm;            // 64*192
    float* Ht = sm + 12288;    // [k=j up to 64][row pitch 68]

    const int tid = threadIdx.x, tx = tid & 15, ty = tid >> 4;
    for (int i = tid; i < 3072; i += 256)
        ((float4*)Us)[i] = ((const float4*)U)[i];
    for (int i = tid; i < 64 * 68; i += 256) Ht[i] = 0.0f;

    const float4 bz4 = *(const float4*)&bias[192 + 4 * tx];
    const float4 br4 = *(const float4*)&bias[192 + 64 + 4 * tx];
    const float4 bh4 = *(const float4*)&bias[192 + 128 + 4 * tx];
    const float bz[4] = {bz4.x, bz4.y, bz4.z, bz4.w};
    const float br[4] = {br4.x, br4.y, br4.z, br4.w};
    const float bh[4] = {bh4.x, bh4.y, bh4.z, bh4.w};

    const int mode = g_maskMode;
    const int b0 = blockIdx.x * 64;
    __syncthreads();

    for (int t = 0; t < Tn; ++t) {
        float az[4][4] = {}, ar_[4][4] = {}, ah[4][4] = {};
        #pragma unroll 8
        for (int k = 0; k < 64; ++k) {
            const float4 hv4 = *(const float4*)&Ht[k * 68 + 4 * ty];
            const float hv[4] = {hv4.x, hv4.y, hv4.z, hv4.w};
            const float4 uz4 = *(const float4*)&Us[k * 192 + 4 * tx];
            const float4 ur4 = *(const float4*)&Us[k * 192 + 64 + 4 * tx];
            const float4 uh4 = *(const float4*)&Us[k * 192 + 128 + 4 * tx];
            const float uz[4] = {uz4.x, uz4.y, uz4.z, uz4.w};
            const float ur[4] = {ur4.x, ur4.y, ur4.z, ur4.w};
            const float uh[4] = {uh4.x, uh4.y, uh4.z, uh4.w};
            #pragma unroll
            for (int i = 0; i < 4; ++i)
                #pragma unroll
                for (int j = 0; j < 4; ++j) {
                    az[i][j] += hv[i] * uz[j];
                    ar_[i][j] += hv[i] * ur[j];
                    ah[i][j] += hv[i] * uh[j];
                }
        }
        __syncthreads();   // all GEMM reads of Ht complete

        float hnew[4][4];
        #pragma unroll
        for (int i = 0; i < 4; ++i) {
            const int b = b0 + 4 * ty + i;
            const float m = mval(mask, b * Tn + t, mode);
            const int xbase = (b * Tn + t) * 192;
            const float4 xz4 = *(const float4*)&g_xproj[xbase + 4 * tx];
            const float4 xr4 = *(const float4*)&g_xproj[xbase + 64 + 4 * tx];
            const float4 xh4 = *(const float4*)&g_xproj[xbase + 128 + 4 * tx];
            const float xz[4] = {xz4.x, xz4.y, xz4.z, xz4.w};
            const float xr[4] = {xr4.x, xr4.y, xr4.z, xr4.w};
            const float xh[4] = {xh4.x, xh4.y, xh4.z, xh4.w};
            #pragma unroll
            for (int jj = 0; jj < 4; ++jj) {
                const float ho = Ht[(4 * tx + jj) * 68 + 4 * ty + i];
                const float z = sigf(xz[jj] + bz[jj] + az[i][jj]);
                const float r = sigf(xr[jj] + br[jj] + ar_[i][jj]);
                const float hh = tanhf_(xh[jj] + bh[jj] + r * ah[i][jj]);
                const float hn = z * ho + (1.0f - z) * hh;
                hnew[i][jj] = (m != 0.0f) ? hn : ho;   // exact jnp.where semantics
            }
            float4 o; o.x = hnew[i][0]; o.y = hnew[i][1];
            o.z = hnew[i][2]; o.w = hnew[i][3];
            *(float4*)&y[(b * Tn + t) * 64 + 4 * tx] = o;
        }
        #pragma unroll
        for (int jj = 0; jj < 4; ++jj) {
            float4 o; o.x = hnew[0][jj]; o.y = hnew[1][jj];
            o.z = hnew[2][jj]; o.w = hnew[3][jj];
            *(float4*)&Ht[(4 * tx + jj) * 68 + 4 * ty] = o;
        }
        __syncthreads();   // Ht updated before next step's GEMM
    }
}

// -------- twin MLP + masked aux loss. One warp per batch row (8192 warps). --------
__global__ void __launch_bounds__(256, 1) mlp_k(
    const float* __restrict__ ub, const float* __restrict__ nub,
    const void* __restrict__ nmask,
    const float* __restrict__ w1, const float* __restrict__ b1,
    const float* __restrict__ w2, const float* __restrict__ b2,
    const float* __restrict__ w3, const float* __restrict__ b3,
    const float* __restrict__ y)
{
    extern __shared__ float sm[];
    float* w1s = sm;             // 16384
    float* w2s = w1s + 16384;    // 8192
    float* w3s = w2s + 8192;     // 64
    float* b1s = w3s + 64;       // 128
    float* b2s = b1s + 128;      // 64
    float* red = b2s + 64;       // 16
    float* h1  = red + 16;       // 8 warps x 256

    const int tid = threadIdx.x, lane = tid & 31, wp = tid >> 5;
    for (int i = tid; i < 4096; i += 256) ((float4*)w1s)[i] = ((const float4*)w1)[i];
    for (int i = tid; i < 2048; i += 256) ((float4*)w2s)[i] = ((const float4*)w2)[i];
    if (tid < 64) w3s[tid] = w3[tid];
    if (tid < 128) b1s[tid] = b1[tid];
    if (tid >= 128 && tid < 192) b2s[tid - 128] = b2[tid - 128];
    __syncthreads();

    const int mode = g_maskMode;
    const float b3v = b3[0];
    const float loge = logf(1e-7f);
    const float log1me = logf(1.0f - 1e-7f);
    float* h1w = h1 + wp * 256;
    const int b = blockIdx.x * 8 + wp;           // 0..8191

    float accL = 0.0f, accC = 0.0f;
    for (int tt = 0; tt < 39; ++tt) {
        const float* gp = y   + (b * 40 + 1 + tt) * 64;
        const float* xp = ub  + (b * 40 + 1 + tt) * 64;
        const float* np = nub + (b * 39 + tt) * 64;
        const float g0 = gp[lane], g1 = gp[lane + 32];
        const float x0 = xp[lane], x1 = xp[lane + 32];
        const float n0 = np[lane], n1 = np[lane + 32];

        float ag[4] = {}, ax[4] = {}, an[4] = {};
        #pragma unroll 16
        for (int k = 0; k < 64; ++k) {
            const float gk = __shfl_sync(0xffffffffu, k < 32 ? g0 : g1, k & 31);
            const float xk = __shfl_sync(0xffffffffu, k < 32 ? x0 : x1, k & 31);
            const float nk = __shfl_sync(0xffffffffu, k < 32 ? n0 : n1, k & 31);
            const float4 wa4 = *(const float4*)&w1s[k * 128 + 4 * lane];
            const float4 wb4 = *(const float4*)&w1s[(64 + k) * 128 + 4 * lane];
            const float wa[4] = {wa4.x, wa4.y, wa4.z, wa4.w};
            const float wb[4] = {wb4.x, wb4.y, wb4.z, wb4.w};
            #pragma unroll
            for (int j = 0; j < 4; ++j) {
                ag[j] += gk * wa[j];
                ax[j] += xk * wb[j];
                an[j] += nk * wb[j];
            }
        }
        const float4 bv4 = *(const float4*)&b1s[4 * lane];
        const float bv[4] = {bv4.x, bv4.y, bv4.z, bv4.w};
        float hp[4], hn[4];
        #pragma unroll
        for (int j = 0; j < 4; ++j) {
            hp[j] = fmaxf(ag[j] + ax[j] + bv[j], 0.0f);
            hn[j] = fmaxf(ag[j] + an[j] + bv[j], 0.0f);
        }
        { float4 o; o.x = hp[0]; o.y = hp[1]; o.z = hp[2]; o.w = hp[3];
          *(float4*)&h1w[4 * lane] = o;
          o.x = hn[0]; o.y = hn[1]; o.z = hn[2]; o.w = hn[3];
          *(float4*)&h1w[128 + 4 * lane] = o; }
        __syncwarp();

        float ap0 = 0.f, ap1 = 0.f, aq0 = 0.f, aq1 = 0.f;
        #pragma unroll 8
        for (int k = 0; k < 128; ++k) {
            const float hpk = h1w[k], hnk = h1w[128 + k];
            const float2 wv = *(const float2*)&w2s[k * 64 + 2 * lane];
            ap0 += hpk * wv.x; ap1 += hpk * wv.y;
            aq0 += hnk * wv.x; aq1 += hnk * wv.y;
        }
        const float h2p0 = fmaxf(ap0 + b2s[2 * lane], 0.0f);
        const float h2p1 = fmaxf(ap1 + b2s[2 * lane + 1], 0.0f);
        const float h2n0 = fmaxf(aq0 + b2s[2 * lane], 0.0f);
        const float h2n1 = fmaxf(aq1 + b2s[2 * lane + 1], 0.0f);
        float sp = h2p0 * w3s[2 * lane] + h2p1 * w3s[2 * lane + 1];
        float sn = h2n0 * w3s[2 * lane] + h2n1 * w3s[2 * lane + 1];
        #pragma unroll
        for (int off = 16; off; off >>= 1) {
            sp += __shfl_xor_sync(0xffffffffu, sp, off);
            sn += __shfl_xor_sync(0xffffffffu, sn, off);
        }
        const float p  = sigf(sp + b3v);
        const float pn = sigf(sn + b3v);
        const float lp = -(p * log1me + (1.0f - p) * loge);
        const float ln = -(pn * loge + (1.0f - pn) * log1me);
        const float m = mval(nmask, b * 39 + tt, mode);
        accL += m * (lp + ln);
        accC += m;
        __syncwarp();   // h1w reuse next iteration
    }
    if (lane == 0) { red[wp] = accL; red[8 + wp] = accC; }
    __syncthreads();
    if (tid == 0) {
        float L = 0.f, C = 0.f;
        for (int i = 0; i < 8; ++i) { L += red[i]; C += red[8 + i]; }
        g_partials[blockIdx.x] = L;
        g_partials[1024 + blockIdx.x] = C;
    }
}

// -------- deterministic final reduction --------
__global__ void fin_k(float* __restrict__ out, int out_size) {
    float L = 0.f, C = 0.f;
    for (int i = 0; i < 1024; ++i) { L += g_partials[i]; C += g_partials[1024 + i]; }
    const float cnt = fmaxf(C, 1.0f);
    out[out_size - 1] = L / (2.0f * cnt);
}

extern "C" void kernel_launch(void* const* d_in, const int* in_sizes, int n_in,
                              void* d_out, int out_size) {
    const float* ub    = (const float*)d_in[0];   // user_behavior (B,T,E)
    const void*  mask  = d_in[1];                 // mask_bool (B,T)
    const float* nub   = (const float*)d_in[2];   // neg_user_behavior (B,T-1,E)
    const void*  nmask = d_in[3];                 // neg_mask_bool (B,T-1)
    const float* W     = (const float*)d_in[4];   // gru_kernel (64,192)
    const float* U     = (const float*)d_in[5];   // gru_rkernel (64,192)
    const float* bias  = (const float*)d_in[6];   // gru_bias (2,192)
    const float* w1    = (const float*)d_in[7];
    const float* b1    = (const float*)d_in[8];
    const float* w2    = (const float*)d_in[9];
    const float* b2    = (const float*)d_in[10];
    const float* w3    = (const float*)d_in[11];
    const float* b3    = (const float*)d_in[12];
    float* y = (float*)d_out;

    cudaFuncSetAttribute(xproj_k, cudaFuncAttributeMaxDynamicSharedMemorySize, XP_SMEM);
    cudaFuncSetAttribute(gru_k,   cudaFuncAttributeMaxDynamicSharedMemorySize, GRU_SMEM);
    cudaFuncSetAttribute(mlp_k,   cudaFuncAttributeMaxDynamicSharedMemorySize, MLP_SMEM);

    detect_k<<<1, 256>>>((const int*)mask);
    xproj_k<<<1280, 256, XP_SMEM>>>(ub, W, bias);
    gru_k<<<128, 256, GRU_SMEM>>>(mask, U, bias, y);
    mlp_k<<<1024, 256, MLP_SMEM>>>(ub, nub, nmask, w1, b1, w2, b2, w3, b3, y);
    fin_k<<<1, 1>>>(y, out_size);
}

// round 4
// speedup vs baseline: 1.4550x; 1.4550x over previous
#include <cuda_runtime.h>
#include <cuda_bf16.h>
#include <math.h>

// Problem constants
#define Bn 8192
#define Tn 40
#define En 64
#define ROWS (Bn*Tn)              // 327680
#define NTILES 4992               // ceil(8192*39/64)

#define XP_SMEM  ((12288 + 64*68)*4)   // 66560 B
#define GRU_SMEM ((12288 + 64*68)*4)   // 66560 B
#define MLP_SMEM (55376*4)             // 221504 B

// -------- device scratch (no allocations allowed) --------
__device__ float g_xproj[(size_t)ROWS * 192];   // 240 MB
__device__ int   g_maskMode;                    // 0=u8, 1=int32, 2=float32
__device__ float g_partials[NTILES];
__device__ int   g_tasks[NTILES * 64];
__device__ int   g_nm;

__device__ __forceinline__ float mval(const void* m, int idx, int mode) {
    if (mode == 1) return ((const int*)m)[idx] ? 1.0f : 0.0f;
    if (mode == 2) return ((const float*)m)[idx];
    return ((const unsigned char*)m)[idx] ? 1.0f : 0.0f;
}
__device__ __forceinline__ float sigf(float v) { return 1.0f / (1.0f + __expf(-v)); }
__device__ __forceinline__ float tanhf_(float v) {
    return 1.0f - 2.0f / (__expf(2.0f * v) + 1.0f);
}

// packed f32x2 helpers
__device__ __forceinline__ unsigned long long dup2(float x) {
    unsigned long long r; unsigned u = __float_as_uint(x);
    asm("mov.b64 %0, {%1, %1};" : "=l"(r) : "r"(u));
    return r;
}
__device__ __forceinline__ void fma2(unsigned long long& d,
                                     unsigned long long a, unsigned long long b) {
    asm("fma.rn.f32x2 %0, %1, %2, %0;" : "+l"(d) : "l"(a), "l"(b));
}
__device__ __forceinline__ float2 unp(unsigned long long v) {
    unsigned lo, hi;
    asm("mov.b64 {%0, %1}, %2;" : "=r"(lo), "=r"(hi) : "l"(v));
    return make_float2(__uint_as_float(lo), __uint_as_float(hi));
}

// -------- mask dtype probe (reads only within smallest candidate buffer) --------
__global__ void detect_k(const int* __restrict__ m32) {
    __shared__ int sB, sF;
    if (threadIdx.x == 0) { sB = 1; sF = 1; }
    __syncthreads();
    int okB = 1, okF = 1;
    for (int i = threadIdx.x; i < 2560; i += blockDim.x) {
        int v = m32[i];
        okB = okB && (v == 0 || v == 1);
        okF = okF && (v == 0 || v == 0x3F800000);
    }
    atomicAnd(&sB, okB);
    atomicAnd(&sF, okF);
    __syncthreads();
    if (threadIdx.x == 0) g_maskMode = sB ? 1 : (sF ? 2 : 0);
}

// -------- build compacted MLP task list (valid tts are a prefix per row) --------
__global__ void scan_k(const void* __restrict__ nmask) {
    __shared__ int ssum[256];
    const int tid = threadIdx.x, mode = g_maskMode;
    int cnt[32]; int tot = 0;
    #pragma unroll
    for (int r = 0; r < 32; ++r) {
        const int b = tid * 32 + r;
        int c = 0;
        for (int tt = 0; tt < 39; ++tt)
            c += (mval(nmask, b * 39 + tt, mode) != 0.0f);
        cnt[r] = c; tot += c;
    }
    ssum[tid] = tot; __syncthreads();
    for (int off = 1; off < 256; off <<= 1) {
        int v = (tid >= off) ? ssum[tid - off] : 0;
        __syncthreads();
        ssum[tid] += v;
        __syncthreads();
    }
    int base = ssum[tid] - tot;             // exclusive prefix
    const int total = ssum[255];
    #pragma unroll
    for (int r = 0; r < 32; ++r) {
        const int b = tid * 32 + r;
        for (int tt = 0; tt < cnt[r]; ++tt) g_tasks[base + tt] = (b << 6) | tt;
        base += cnt[r];
    }
    __syncthreads();
    const int padded = ((total + 63) >> 6) << 6;
    for (int i = total + tid; i < padded; i += 256) g_tasks[i] = -1;
    if (tid == 0) g_nm = total;
}

// -------- xproj = x @ W + bi  (M=327680, K=64, N=192), FFMA2 core --------
__global__ void __launch_bounds__(256, 1) xproj_k(
    const float* __restrict__ x, const float* __restrict__ W,
    const float* __restrict__ bias)
{
    extern __shared__ float sm[];
    float* Ws = sm;            // 64*192
    float* XT = sm + 12288;    // [k][row pitch 68]

    const int tid = threadIdx.x;
    for (int i = tid; i < 3072; i += 256)
        ((float4*)Ws)[i] = ((const float4*)W)[i];

    const int tx = tid & 15, ty = tid >> 4;
    const float4 ba = *(const float4*)&bias[4 * tx];
    const float4 bb = *(const float4*)&bias[64 + 4 * tx];
    const float4 bc = *(const float4*)&bias[128 + 4 * tx];
    const float bav[4] = {ba.x, ba.y, ba.z, ba.w};
    const float bbv[4] = {bb.x, bb.y, bb.z, bb.w};
    const float bcv[4] = {bc.x, bc.y, bc.z, bc.w};

    for (int tile = 0; tile < 4; ++tile) {
        const int r0 = (blockIdx.x * 4 + tile) * 64;
        __syncthreads();
        for (int i = tid; i < 1024; i += 256) {
            const int row = i >> 4, kq = i & 15;
            const float4 v = *(const float4*)&x[(size_t)(r0 + row) * 64 + 4 * kq];
            XT[(4 * kq + 0) * 68 + row] = v.x;
            XT[(4 * kq + 1) * 68 + row] = v.y;
            XT[(4 * kq + 2) * 68 + row] = v.z;
            XT[(4 * kq + 3) * 68 + row] = v.w;
        }
        __syncthreads();

        unsigned long long az[2][4] = {}, ar2[2][4] = {}, ah[2][4] = {};
        #pragma unroll 8
        for (int k = 0; k < 64; ++k) {
            const ulonglong2 h2 = *(const ulonglong2*)&XT[k * 68 + 4 * ty];
            const float4 uz4 = *(const float4*)&Ws[k * 192 + 4 * tx];
            const float4 ur4 = *(const float4*)&Ws[k * 192 + 64 + 4 * tx];
            const float4 uh4 = *(const float4*)&Ws[k * 192 + 128 + 4 * tx];
            const float uzv[4] = {uz4.x, uz4.y, uz4.z, uz4.w};
            const float urv[4] = {ur4.x, ur4.y, ur4.z, ur4.w};
            const float uhv[4] = {uh4.x, uh4.y, uh4.z, uh4.w};
            #pragma unroll
            for (int j = 0; j < 4; ++j) {
                unsigned long long w;
                w = dup2(uzv[j]); fma2(az[0][j], h2.x, w); fma2(az[1][j], h2.y, w);
                w = dup2(urv[j]); fma2(ar2[0][j], h2.x, w); fma2(ar2[1][j], h2.y, w);
                w = dup2(uhv[j]); fma2(ah[0][j], h2.x, w); fma2(ah[1][j], h2.y, w);
            }
        }
        float azs[4][4], ars[4][4], ahs[4][4];
        #pragma unroll
        for (int p = 0; p < 2; ++p)
            #pragma unroll
            for (int j = 0; j < 4; ++j) {
                float2 v;
                v = unp(az[p][j]);  azs[2*p][j] = v.x; azs[2*p+1][j] = v.y;
                v = unp(ar2[p][j]); ars[2*p][j] = v.x; ars[2*p+1][j] = v.y;
                v = unp(ah[p][j]);  ahs[2*p][j] = v.x; ahs[2*p+1][j] = v.y;
            }
        #pragma unroll
        for (int i = 0; i < 4; ++i) {
            const size_t base = (size_t)(r0 + 4 * ty + i) * 192;
            float4 o;
            o.x = azs[i][0] + bav[0]; o.y = azs[i][1] + bav[1];
            o.z = azs[i][2] + bav[2]; o.w = azs[i][3] + bav[3];
            *(float4*)&g_xproj[base + 4 * tx] = o;
            o.x = ars[i][0] + bbv[0]; o.y = ars[i][1] + bbv[1];
            o.z = ars[i][2] + bbv[2]; o.w = ars[i][3] + bbv[3];
            *(float4*)&g_xproj[base + 64 + 4 * tx] = o;
            o.x = ahs[i][0] + bcv[0]; o.y = ahs[i][1] + bcv[1];
            o.z = ahs[i][2] + bcv[2]; o.w = ahs[i][3] + bcv[3];
            *(float4*)&g_xproj[base + 128 + 4 * tx] = o;
        }
    }
}

// -------- GRU recurrence: 128 CTAs x 64 batch rows, FFMA2 per-step GEMM --------
__global__ void __launch_bounds__(256, 1) gru_k(
    const void* __restrict__ mask, const float* __restrict__ U,
    const float* __restrict__ bias, float* __restrict__ y)
{
    extern __shared__ float sm[];
    float* Us = sm;            // 64*192
    float* Ht = sm + 12288;    // [col j][row pitch 68]

    const int tid = threadIdx.x, tx = tid & 15, ty = tid >> 4;
    for (int i = tid; i < 3072; i += 256)
        ((float4*)Us)[i] = ((const float4*)U)[i];
    for (int i = tid; i < 64 * 68; i += 256) Ht[i] = 0.0f;

    const float4 bz4 = *(const float4*)&bias[192 + 4 * tx];
    const float4 br4 = *(const float4*)&bias[192 + 64 + 4 * tx];
    const float4 bh4 = *(const float4*)&bias[192 + 128 + 4 * tx];
    const float bz[4] = {bz4.x, bz4.y, bz4.z, bz4.w};
    const float br[4] = {br4.x, br4.y, br4.z, br4.w};
    const float bh[4] = {bh4.x, bh4.y, bh4.z, bh4.w};

    const int mode = g_maskMode;
    const int b0 = blockIdx.x * 64;
    __syncthreads();

    for (int t = 0; t < Tn; ++t) {
        unsigned long long az[2][4] = {}, ar2[2][4] = {}, ah[2][4] = {};
        #pragma unroll 8
        for (int k = 0; k < 64; ++k) {
            const ulonglong2 h2 = *(const ulonglong2*)&Ht[k * 68 + 4 * ty];
            const float4 uz4 = *(const float4*)&Us[k * 192 + 4 * tx];
            const float4 ur4 = *(const float4*)&Us[k * 192 + 64 + 4 * tx];
            const float4 uh4 = *(const float4*)&Us[k * 192 + 128 + 4 * tx];
            const float uzv[4] = {uz4.x, uz4.y, uz4.z, uz4.w};
            const float urv[4] = {ur4.x, ur4.y, ur4.z, ur4.w};
            const float uhv[4] = {uh4.x, uh4.y, uh4.z, uh4.w};
            #pragma unroll
            for (int j = 0; j < 4; ++j) {
                unsigned long long w;
                w = dup2(uzv[j]); fma2(az[0][j], h2.x, w); fma2(az[1][j], h2.y, w);
                w = dup2(urv[j]); fma2(ar2[0][j], h2.x, w); fma2(ar2[1][j], h2.y, w);
                w = dup2(uhv[j]); fma2(ah[0][j], h2.x, w); fma2(ah[1][j], h2.y, w);
            }
        }
        __syncthreads();   // all GEMM reads of Ht complete

        float azs[4][4], ars[4][4], ahs[4][4];
        #pragma unroll
        for (int p = 0; p < 2; ++p)
            #pragma unroll
            for (int j = 0; j < 4; ++j) {
                float2 v;
                v = unp(az[p][j]);  azs[2*p][j] = v.x; azs[2*p+1][j] = v.y;
                v = unp(ar2[p][j]); ars[2*p][j] = v.x; ars[2*p+1][j] = v.y;
                v = unp(ah[p][j]);  ahs[2*p][j] = v.x; ahs[2*p+1][j] = v.y;
            }

        float hnew[4][4];
        #pragma unroll
        for (int i = 0; i < 4; ++i) {
            const int b = b0 + 4 * ty + i;
            const float m = mval(mask, b * Tn + t, mode);
            const int xbase = (b * Tn + t) * 192;
            const float4 xz4 = *(const float4*)&g_xproj[xbase + 4 * tx];
            const float4 xr4 = *(const float4*)&g_xproj[xbase + 64 + 4 * tx];
            const float4 xh4 = *(const float4*)&g_xproj[xbase + 128 + 4 * tx];
            const float xz[4] = {xz4.x, xz4.y, xz4.z, xz4.w};
            const float xr[4] = {xr4.x, xr4.y, xr4.z, xr4.w};
            const float xh[4] = {xh4.x, xh4.y, xh4.z, xh4.w};
            #pragma unroll
            for (int jj = 0; jj < 4; ++jj) {
                const float ho = Ht[(4 * tx + jj) * 68 + 4 * ty + i];
                const float z = sigf(xz[jj] + bz[jj] + azs[i][jj]);
                const float r = sigf(xr[jj] + br[jj] + ars[i][jj]);
                const float hh = tanhf_(xh[jj] + bh[jj] + r * ahs[i][jj]);
                const float hn = z * ho + (1.0f - z) * hh;
                hnew[i][jj] = (m != 0.0f) ? hn : ho;
            }
            float4 o; o.x = hnew[i][0]; o.y = hnew[i][1];
            o.z = hnew[i][2]; o.w = hnew[i][3];
            *(float4*)&y[(b * Tn + t) * 64 + 4 * tx] = o;
        }
        #pragma unroll
        for (int jj = 0; jj < 4; ++jj) {
            #pragma unroll
            for (int i = 0; i < 4; ++i)
                Ht[(4 * tx + jj) * 68 + 4 * ty + i] = hnew[i][jj];
        }
        __syncthreads();   // Ht updated before next step's GEMM
    }
}

// -------- tiled twin-MLP over compacted tasks (64 tasks/CTA) + masked loss --------
__global__ void __launch_bounds__(256, 1) mlp_k(
    const float* __restrict__ ub, const float* __restrict__ nub,
    const float* __restrict__ w1, const float* __restrict__ b1,
    const float* __restrict__ w2, const float* __restrict__ b2,
    const float* __restrict__ w3, const float* __restrict__ b3,
    const float* __restrict__ y)
{
    extern __shared__ float sm[];
    float* W1s = sm;                 // 16384  [k][j=128]
    float* W2s = W1s + 16384;        // 8192   [k][j=64]
    float* GT  = W2s + 8192;         // 4352   [k][row 68]
    float* XT  = GT + 4352;          // 4352
    float* NT  = XT + 4352;          // 4352
    float* H1p = NT + 4352;          // 8704   [j=128][row 68]
    float* H1n = H1p + 8704;         // 8704
    float* b1s = H1n + 8704;         // 128
    float* b2s = b1s + 128;          // 64
    float* w3s = b2s + 64;           // 64
    float* red = w3s + 64;           // 16
    int*   tsk = (int*)(red + 16);   // 64

    const int tid = threadIdx.x, tx = tid & 15, ty = tid >> 4;
    const int tile0 = blockIdx.x * 64;

    const int nm = g_nm;
    if (tile0 >= nm) { if (tid == 0) g_partials[blockIdx.x] = 0.0f; return; }

    if (tid < 64) tsk[tid] = g_tasks[tile0 + tid];
    for (int i = tid; i < 4096; i += 256) ((float4*)W1s)[i] = ((const float4*)w1)[i];
    for (int i = tid; i < 2048; i += 256) ((float4*)W2s)[i] = ((const float4*)w2)[i];
    if (tid < 128) b1s[tid] = b1[tid];
    if (tid >= 128 && tid < 192) b2s[tid - 128] = b2[tid - 128];
    if (tid >= 192 && tid < 256) w3s[tid - 192] = w3[tid - 192];
    __syncthreads();

    // gather + transpose g / x / n tiles (64 tasks x 64 feats)
    for (int i = tid; i < 1024; i += 256) {
        const int row = i >> 4, kq = i & 15;
        int tk = tsk[row]; if (tk < 0) tk = 0;
        const int b = tk >> 6, tt = tk & 63;
        const size_t prow = (size_t)(b * 40 + 1 + tt) * 64 + 4 * kq;
        const size_t nrow = (size_t)(b * 39 + tt) * 64 + 4 * kq;
        float4 v;
        v = *(const float4*)&y[prow];
        GT[(4*kq+0)*68+row]=v.x; GT[(4*kq+1)*68+row]=v.y;
        GT[(4*kq+2)*68+row]=v.z; GT[(4*kq+3)*68+row]=v.w;
        v = *(const float4*)&ub[prow];
        XT[(4*kq+0)*68+row]=v.x; XT[(4*kq+1)*68+row]=v.y;
        XT[(4*kq+2)*68+row]=v.z; XT[(4*kq+3)*68+row]=v.w;
        v = *(const float4*)&nub[nrow];
        NT[(4*kq+0)*68+row]=v.x; NT[(4*kq+1)*68+row]=v.y;
        NT[(4*kq+2)*68+row]=v.z; NT[(4*kq+3)*68+row]=v.w;
    }
    __syncthreads();

    // layer 1: two j-passes of 64 cols each
    #pragma unroll
    for (int pass = 0; pass < 2; ++pass) {
        const int j0 = 4 * tx + 64 * pass;
        unsigned long long ag[2][4] = {}, ax[2][4] = {}, an[2][4] = {};
        #pragma unroll 4
        for (int k = 0; k < 64; ++k) {
            const ulonglong2 g2 = *(const ulonglong2*)&GT[k * 68 + 4 * ty];
            const ulonglong2 x2 = *(const ulonglong2*)&XT[k * 68 + 4 * ty];
            const ulonglong2 n2 = *(const ulonglong2*)&NT[k * 68 + 4 * ty];
            const float4 wa4 = *(const float4*)&W1s[k * 128 + j0];
            const float4 wb4 = *(const float4*)&W1s[(64 + k) * 128 + j0];
            const float wav[4] = {wa4.x, wa4.y, wa4.z, wa4.w};
            const float wbv[4] = {wb4.x, wb4.y, wb4.z, wb4.w};
            #pragma unroll
            for (int j = 0; j < 4; ++j) {
                unsigned long long w;
                w = dup2(wav[j]);
                fma2(ag[0][j], g2.x, w); fma2(ag[1][j], g2.y, w);
                w = dup2(wbv[j]);
                fma2(ax[0][j], x2.x, w); fma2(ax[1][j], x2.y, w);
                fma2(an[0][j], n2.x, w); fma2(an[1][j], n2.y, w);
            }
        }
        #pragma unroll
        for (int p = 0; p < 2; ++p)
            #pragma unroll
            for (int j = 0; j < 4; ++j) {
                const float2 gv = unp(ag[p][j]);
                const float2 xv = unp(ax[p][j]);
                const float2 nv = unp(an[p][j]);
                const float bb = b1s[j0 + j];
                const int r0 = 4 * ty + 2 * p;
                H1p[(j0+j)*68 + r0    ] = fmaxf(gv.x + xv.x + bb, 0.0f);
                H1p[(j0+j)*68 + r0 + 1] = fmaxf(gv.y + xv.y + bb, 0.0f);
                H1n[(j0+j)*68 + r0    ] = fmaxf(gv.x + nv.x + bb, 0.0f);
                H1n[(j0+j)*68 + r0 + 1] = fmaxf(gv.y + nv.y + bb, 0.0f);
            }
    }
    __syncthreads();

    // layer 2 (k=128) + layer 3 + loss
    unsigned long long accp[2][4] = {}, accn[2][4] = {};
    #pragma unroll 4
    for (int k = 0; k < 128; ++k) {
        const ulonglong2 hp2 = *(const ulonglong2*)&H1p[k * 68 + 4 * ty];
        const ulonglong2 hn2 = *(const ulonglong2*)&H1n[k * 68 + 4 * ty];
        const float4 w4 = *(const float4*)&W2s[k * 64 + 4 * tx];
        const float wv[4] = {w4.x, w4.y, w4.z, w4.w};
        #pragma unroll
        for (int j = 0; j < 4; ++j) {
            const unsigned long long w = dup2(wv[j]);
            fma2(accp[0][j], hp2.x, w); fma2(accp[1][j], hp2.y, w);
            fma2(accn[0][j], hn2.x, w); fma2(accn[1][j], hn2.y, w);
        }
    }
    float sp[4] = {0,0,0,0}, sn[4] = {0,0,0,0};
    #pragma unroll
    for (int p = 0; p < 2; ++p)
        #pragma unroll
        for (int j = 0; j < 4; ++j) {
            const float2 pv = unp(accp[p][j]);
            const float2 nv = unp(accn[p][j]);
            const float bb = b2s[4 * tx + j], wv3 = w3s[4 * tx + j];
            sp[2*p]   += fmaxf(pv.x + bb, 0.0f) * wv3;
            sp[2*p+1] += fmaxf(pv.y + bb, 0.0f) * wv3;
            sn[2*p]   += fmaxf(nv.x + bb, 0.0f) * wv3;
            sn[2*p+1] += fmaxf(nv.y + bb, 0.0f) * wv3;
        }
    #pragma unroll
    for (int off = 1; off < 16; off <<= 1) {
        #pragma unroll
        for (int i = 0; i < 4; ++i) {
            sp[i] += __shfl_xor_sync(0xffffffffu, sp[i], off);
            sn[i] += __shfl_xor_sync(0xffffffffu, sn[i], off);
        }
    }
    if (tx == 0) {
        const float b3v = b3[0];
        const float loge = logf(1e-7f);
        const float log1me = logf(1.0f - 1e-7f);
        float accL = 0.0f;
        #pragma unroll
        for (int i = 0; i < 4; ++i) {
            const int row = 4 * ty + i;
            if (tsk[row] >= 0) {
                const float p  = sigf(sp[i] + b3v);
                const float pn = sigf(sn[i] + b3v);
                const float lp = -(p  * log1me + (1.0f - p)  * loge);
                const float ln = -(pn * loge  + (1.0f - pn) * log1me);
                accL += lp + ln;
            }
        }
        red[ty] = accL;
    }
    __syncthreads();
    if (tid == 0) {
        float L = 0.0f;
        #pragma unroll
        for (int i = 0; i < 16; ++i) L += red[i];
        g_partials[blockIdx.x] = L;
    }
}

// -------- deterministic final reduction --------
__global__ void fin_k(float* __restrict__ out, int out_size) {
    __shared__ float s[256];
    float L = 0.0f;
    for (int i = threadIdx.x; i < NTILES; i += 256) L += g_partials[i];
    s[threadIdx.x] = L; __syncthreads();
    for (int off = 128; off; off >>= 1) {
        if (threadIdx.x < off) s[threadIdx.x] += s[threadIdx.x + off];
        __syncthreads();
    }
    if (threadIdx.x == 0) {
        const float cnt = fmaxf((float)g_nm, 1.0f);
        out[out_size - 1] = s[0] / (2.0f * cnt);
    }
}

extern "C" void kernel_launch(void* const* d_in, const int* in_sizes, int n_in,
                              void* d_out, int out_size) {
    const float* ub    = (const float*)d_in[0];
    const void*  mask  = d_in[1];
    const float* nub   = (const float*)d_in[2];
    const void*  nmask = d_in[3];
    const float* W     = (const float*)d_in[4];
    const float* U     = (const float*)d_in[5];
    const float* bias  = (const float*)d_in[6];
    const float* w1    = (const float*)d_in[7];
    const float* b1    = (const float*)d_in[8];
    const float* w2    = (const float*)d_in[9];
    const float* b2    = (const float*)d_in[10];
    const float* w3    = (const float*)d_in[11];
    const float* b3    = (const float*)d_in[12];
    float* y = (float*)d_out;

    cudaFuncSetAttribute(xproj_k, cudaFuncAttributeMaxDynamicSharedMemorySize, XP_SMEM);
    cudaFuncSetAttribute(gru_k,   cudaFuncAttributeMaxDynamicSharedMemorySize, GRU_SMEM);
    cudaFuncSetAttribute(mlp_k,   cudaFuncAttributeMaxDynamicSharedMemorySize, MLP_SMEM);

    detect_k<<<1, 256>>>((const int*)mask);
    scan_k<<<1, 256>>>(nmask);
    xproj_k<<<1280, 256, XP_SMEM>>>(ub, W, bias);
    gru_k<<<128, 256, GRU_SMEM>>>(mask, U, bias, y);
    mlp_k<<<NTILES, 256, MLP_SMEM>>>(ub, nub, w1, b1, w2, b2, w3, b3, y);
    fin_k<<<1, 256>>>(y, out_size);
}

// round 5
// speedup vs baseline: 1.8662x; 1.2826x over previous
#include <cuda_runtime.h>
#include <cuda_bf16.h>
#include <math.h>

// Problem constants
#define Bn 8192
#define Tn 40
#define En 64
#define ROWS (Bn*Tn)              // 327680
#define NTILES 4992               // ceil(8192*39/64)

#define XP_SMEM  ((12288 + 64*68)*4)   // 66560 B
#define GRU_SMEM ((12288 + 2*64*66)*4) // 82944 B
#define MLP_SMEM (55392*4)             // 221568 B

// -------- device scratch (no allocations allowed) --------
__device__ float g_xproj[(size_t)ROWS * 192];   // 240 MB
__device__ int   g_maskMode;                    // 0=u8, 1=int32, 2=float32
__device__ float g_partials[NTILES];
__device__ int   g_tasks[NTILES * 64];
__device__ int   g_cnt[Bn];
__device__ int   g_off[Bn];
__device__ int   g_nm;

__device__ __forceinline__ float mval(const void* m, int idx, int mode) {
    if (mode == 1) return ((const int*)m)[idx] ? 1.0f : 0.0f;
    if (mode == 2) return ((const float*)m)[idx];
    return ((const unsigned char*)m)[idx] ? 1.0f : 0.0f;
}
__device__ __forceinline__ float sigf(float v) { return 1.0f / (1.0f + __expf(-v)); }
__device__ __forceinline__ float tanhf_(float v) {
    return 1.0f - 2.0f / (__expf(2.0f * v) + 1.0f);
}

// packed f32x2 helpers
__device__ __forceinline__ unsigned long long dup2(float x) {
    unsigned long long r; unsigned u = __float_as_uint(x);
    asm("mov.b64 %0, {%1, %1};" : "=l"(r) : "r"(u));
    return r;
}
__device__ __forceinline__ void fma2(unsigned long long& d,
                                     unsigned long long a, unsigned long long b) {
    asm("fma.rn.f32x2 %0, %1, %2, %0;" : "+l"(d) : "l"(a), "l"(b));
}
__device__ __forceinline__ float2 unp(unsigned long long v) {
    unsigned lo, hi;
    asm("mov.b64 {%0, %1}, %2;" : "=r"(lo), "=r"(hi) : "l"(v));
    return make_float2(__uint_as_float(lo), __uint_as_float(hi));
}

// -------- mask dtype probe (reads only within smallest candidate buffer) --------
__global__ void detect_k(const int* __restrict__ m32) {
    __shared__ int sB, sF;
    if (threadIdx.x == 0) { sB = 1; sF = 1; }
    __syncthreads();
    int okB = 1, okF = 1;
    for (int i = threadIdx.x; i < 2560; i += blockDim.x) {
        int v = m32[i];
        okB = okB && (v == 0 || v == 1);
        okF = okF && (v == 0 || v == 0x3F800000);
    }
    atomicAnd(&sB, okB);
    atomicAnd(&sF, okF);
    __syncthreads();
    if (threadIdx.x == 0) g_maskMode = sB ? 1 : (sF ? 2 : 0);
}

// -------- per-row valid-count --------
__global__ void cnt_k(const void* __restrict__ nmask) {
    const int b = blockIdx.x * 256 + threadIdx.x;
    const int mode = g_maskMode;
    int c = 0;
    #pragma unroll
    for (int tt = 0; tt < 39; ++tt)
        c += (mval(nmask, b * 39 + tt, mode) != 0.0f);
    g_cnt[b] = c;
}

// -------- exclusive offsets + tail padding (deterministic) --------
__global__ void off_k() {
    __shared__ int ssum[256];
    const int tid = threadIdx.x;
    int c[32]; int tot = 0;
    #pragma unroll
    for (int r = 0; r < 32; ++r) { c[r] = g_cnt[tid * 32 + r]; tot += c[r]; }
    ssum[tid] = tot; __syncthreads();
    for (int off = 1; off < 256; off <<= 1) {
        int v = (tid >= off) ? ssum[tid - off] : 0;
        __syncthreads();
        ssum[tid] += v;
        __syncthreads();
    }
    int base = ssum[tid] - tot;
    #pragma unroll
    for (int r = 0; r < 32; ++r) { g_off[tid * 32 + r] = base; base += c[r]; }
    const int total = ssum[255];
    const int padded = ((total + 63) >> 6) << 6;
    for (int i = total + tid; i < padded; i += 256) g_tasks[i] = -1;
    if (tid == 0) g_nm = total;
}

// -------- fill compacted task list --------
__global__ void fill_k(const void* __restrict__ nmask) {
    const int b = blockIdx.x * 256 + threadIdx.x;
    const int mode = g_maskMode;
    int off = g_off[b];
    #pragma unroll
    for (int tt = 0; tt < 39; ++tt)
        if (mval(nmask, b * 39 + tt, mode) != 0.0f) g_tasks[off++] = (b << 6) | tt;
}

// -------- xproj = x @ W + bi  (M=327680, K=64, N=192), FFMA2 core --------
__global__ void __launch_bounds__(256, 2) xproj_k(
    const float* __restrict__ x, const float* __restrict__ W,
    const float* __restrict__ bias)
{
    extern __shared__ float sm[];
    float* Ws = sm;            // 64*192
    float* XT = sm + 12288;    // [k][row pitch 68]

    const int tid = threadIdx.x;
    for (int i = tid; i < 3072; i += 256)
        ((float4*)Ws)[i] = ((const float4*)W)[i];

    const int tx = tid & 15, ty = tid >> 4;
    const float4 ba = *(const float4*)&bias[4 * tx];
    const float4 bb = *(const float4*)&bias[64 + 4 * tx];
    const float4 bc = *(const float4*)&bias[128 + 4 * tx];
    const float bav[4] = {ba.x, ba.y, ba.z, ba.w};
    const float bbv[4] = {bb.x, bb.y, bb.z, bb.w};
    const float bcv[4] = {bc.x, bc.y, bc.z, bc.w};

    for (int tile = 0; tile < 4; ++tile) {
        const int r0 = (blockIdx.x * 4 + tile) * 64;
        __syncthreads();
        for (int i = tid; i < 1024; i += 256) {
            const int row = i >> 4, kq = i & 15;
            const float4 v = *(const float4*)&x[(size_t)(r0 + row) * 64 + 4 * kq];
            XT[(4 * kq + 0) * 68 + row] = v.x;
            XT[(4 * kq + 1) * 68 + row] = v.y;
            XT[(4 * kq + 2) * 68 + row] = v.z;
            XT[(4 * kq + 3) * 68 + row] = v.w;
        }
        __syncthreads();

        // col-pair packing: acc[rowpair? no: row r][colpair cp], rows via dup
        unsigned long long az[4][2] = {}, ar2[4][2] = {}, ah[4][2] = {};
        #pragma unroll 8
        for (int k = 0; k < 64; ++k) {
            const float4 hv4 = *(const float4*)&XT[k * 68 + 4 * ty];
            const float hvv[4] = {hv4.x, hv4.y, hv4.z, hv4.w};
            const ulonglong2 wz = *(const ulonglong2*)&Ws[k * 192 + 4 * tx];
            const ulonglong2 wr = *(const ulonglong2*)&Ws[k * 192 + 64 + 4 * tx];
            const ulonglong2 wh = *(const ulonglong2*)&Ws[k * 192 + 128 + 4 * tx];
            #pragma unroll
            for (int i = 0; i < 4; ++i) {
                const unsigned long long d = dup2(hvv[i]);
                fma2(az[i][0], d, wz.x);  fma2(az[i][1], d, wz.y);
                fma2(ar2[i][0], d, wr.x); fma2(ar2[i][1], d, wr.y);
                fma2(ah[i][0], d, wh.x);  fma2(ah[i][1], d, wh.y);
            }
        }
        #pragma unroll
        for (int i = 0; i < 4; ++i) {
            const size_t base = (size_t)(r0 + 4 * ty + i) * 192;
            float2 v0, v1;
            float4 o;
            v0 = unp(az[i][0]); v1 = unp(az[i][1]);
            o.x = v0.x + bav[0]; o.y = v0.y + bav[1];
            o.z = v1.x + bav[2]; o.w = v1.y + bav[3];
            *(float4*)&g_xproj[base + 4 * tx] = o;
            v0 = unp(ar2[i][0]); v1 = unp(ar2[i][1]);
            o.x = v0.x + bbv[0]; o.y = v0.y + bbv[1];
            o.z = v1.x + bbv[2]; o.w = v1.y + bbv[3];
            *(float4*)&g_xproj[base + 64 + 4 * tx] = o;
            v0 = unp(ah[i][0]); v1 = unp(ah[i][1]);
            o.x = v0.x + bcv[0]; o.y = v0.y + bcv[1];
            o.z = v1.x + bcv[2]; o.w = v1.y + bcv[3];
            *(float4*)&g_xproj[base + 128 + 4 * tx] = o;
        }
    }
}

// -------- GRU: 128 CTAs x 64 rows x 512 threads, double-buffered H --------
// One barrier per step; x-projection prefetched before the GEMM loop.
__global__ void __launch_bounds__(512, 1) gru_k(
    const void* __restrict__ mask, const float* __restrict__ U,
    const float* __restrict__ bias, float* __restrict__ y)
{
    extern __shared__ float sm[];
    float* Us = sm;              // 12288
    float* Ha = sm + 12288;      // 64*66
    float* Hb = Ha + 4224;       // 64*66

    const int tid = threadIdx.x, tx = tid & 15, ty = tid >> 4;  // ty 0..31
    for (int i = tid; i < 3072; i += 512)
        ((float4*)Us)[i] = ((const float4*)U)[i];
    for (int i = tid; i < 4224; i += 512) Ha[i] = 0.0f;

    const float4 bz4 = *(const float4*)&bias[192 + 4 * tx];
    const float4 br4 = *(const float4*)&bias[192 + 64 + 4 * tx];
    const float4 bh4 = *(const float4*)&bias[192 + 128 + 4 * tx];
    const float bz[4] = {bz4.x, bz4.y, bz4.z, bz4.w};
    const float br[4] = {br4.x, br4.y, br4.z, br4.w};
    const float bh[4] = {bh4.x, bh4.y, bh4.z, bh4.w};

    const int mode = g_maskMode;
    const int r0 = blockIdx.x * 64 + 2 * ty;   // this thread's row pair
    __syncthreads();

    float* Hr = Ha;
    float* Hw = Hb;
    for (int t = 0; t < Tn; ++t) {
        // prefetch x-projection + mask for the 2 rows (hidden under GEMM)
        float4 xzp[2], xrp[2], xhp[2]; float mv[2];
        #pragma unroll
        for (int i = 0; i < 2; ++i) {
            const size_t xb = (size_t)((r0 + i) * Tn + t) * 192;
            xzp[i] = *(const float4*)&g_xproj[xb + 4 * tx];
            xrp[i] = *(const float4*)&g_xproj[xb + 64 + 4 * tx];
            xhp[i] = *(const float4*)&g_xproj[xb + 128 + 4 * tx];
            mv[i]  = mval(mask, (r0 + i) * Tn + t, mode);
        }

        unsigned long long az[2][2] = {}, ar2[2][2] = {}, ah[2][2] = {};
        #pragma unroll 8
        for (int k = 0; k < 64; ++k) {
            const float2 hv = *(const float2*)&Hr[k * 66 + 2 * ty];
            const unsigned long long d0 = dup2(hv.x), d1 = dup2(hv.y);
            const ulonglong2 wz = *(const ulonglong2*)&Us[k * 192 + 4 * tx];
            const ulonglong2 wr = *(const ulonglong2*)&Us[k * 192 + 64 + 4 * tx];
            const ulonglong2 wh = *(const ulonglong2*)&Us[k * 192 + 128 + 4 * tx];
            fma2(az[0][0], d0, wz.x);  fma2(az[0][1], d0, wz.y);
            fma2(az[1][0], d1, wz.x);  fma2(az[1][1], d1, wz.y);
            fma2(ar2[0][0], d0, wr.x); fma2(ar2[0][1], d0, wr.y);
            fma2(ar2[1][0], d1, wr.x); fma2(ar2[1][1], d1, wr.y);
            fma2(ah[0][0], d0, wh.x);  fma2(ah[0][1], d0, wh.y);
            fma2(ah[1][0], d1, wh.x);  fma2(ah[1][1], d1, wh.y);
        }

        #pragma unroll
        for (int i = 0; i < 2; ++i) {
            float aZ[4], aR[4], aH[4];
            { float2 v = unp(az[i][0]);  aZ[0] = v.x; aZ[1] = v.y;
              v = unp(az[i][1]);         aZ[2] = v.x; aZ[3] = v.y;
              v = unp(ar2[i][0]);        aR[0] = v.x; aR[1] = v.y;
              v = unp(ar2[i][1]);        aR[2] = v.x; aR[3] = v.y;
              v = unp(ah[i][0]);         aH[0] = v.x; aH[1] = v.y;
              v = unp(ah[i][1]);         aH[2] = v.x; aH[3] = v.y; }
            const float xzv[4] = {xzp[i].x, xzp[i].y, xzp[i].z, xzp[i].w};
            const float xrv[4] = {xrp[i].x, xrp[i].y, xrp[i].z, xrp[i].w};
            const float xhv[4] = {xhp[i].x, xhp[i].y, xhp[i].z, xhp[i].w};
            float hnew[4];
            #pragma unroll
            for (int jj = 0; jj < 4; ++jj) {
                const float ho = Hr[(4 * tx + jj) * 66 + 2 * ty + i];
                const float z = sigf(xzv[jj] + bz[jj] + aZ[jj]);
                const float r = sigf(xrv[jj] + br[jj] + aR[jj]);
                const float hh = tanhf_(xhv[jj] + bh[jj] + r * aH[jj]);
                const float hn = z * ho + (1.0f - z) * hh;
                hnew[jj] = (mv[i] != 0.0f) ? hn : ho;
                Hw[(4 * tx + jj) * 66 + 2 * ty + i] = hnew[jj];
            }
            float4 o; o.x = hnew[0]; o.y = hnew[1]; o.z = hnew[2]; o.w = hnew[3];
            *(float4*)&y[(size_t)((r0 + i) * Tn + t) * 64 + 4 * tx] = o;
        }
        __syncthreads();
        float* tp = Hr; Hr = Hw; Hw = tp;
    }
}

// -------- tiled twin-MLP over compacted tasks (64 tasks/CTA, 512 thr) --------
__global__ void __launch_bounds__(512, 1) mlp_k(
    const float* __restrict__ ub, const float* __restrict__ nub,
    const float* __restrict__ w1, const float* __restrict__ b1,
    const float* __restrict__ w2, const float* __restrict__ b2,
    const float* __restrict__ w3, const float* __restrict__ b3,
    const float* __restrict__ y)
{
    extern __shared__ float sm[];
    float* W1s = sm;                 // 16384  [k][j=128]
    float* W2s = W1s + 16384;        // 8192   [k][j=64]
    float* GT  = W2s + 8192;         // 4352   [k][row 68]
    float* XT  = GT + 4352;          // 4352
    float* NT  = XT + 4352;          // 4352
    float* H1p = NT + 4352;          // 8704   [j=128][row 68]
    float* H1n = H1p + 8704;         // 8704
    float* b1s = H1n + 8704;         // 128
    float* b2s = b1s + 128;          // 64
    float* w3s = b2s + 64;           // 64
    float* red = w3s + 64;           // 32
    int*   tsk = (int*)(red + 32);   // 64

    const int tid = threadIdx.x, tx = tid & 15, ty = tid >> 4;  // ty 0..31
    const int tile0 = blockIdx.x * 64;

    const int nm = g_nm;
    if (tile0 >= nm) { if (tid == 0) g_partials[blockIdx.x] = 0.0f; return; }

    if (tid < 64) tsk[tid] = g_tasks[tile0 + tid];
    for (int i = tid; i < 4096; i += 512) ((float4*)W1s)[i] = ((const float4*)w1)[i];
    for (int i = tid; i < 2048; i += 512) ((float4*)W2s)[i] = ((const float4*)w2)[i];
    if (tid < 128) b1s[tid] = b1[tid];
    if (tid >= 128 && tid < 192) b2s[tid - 128] = b2[tid - 128];
    if (tid >= 192 && tid < 256) w3s[tid - 192] = w3[tid - 192];
    __syncthreads();

    // gather + transpose g / x / n tiles (64 tasks x 64 feats)
    for (int i = tid; i < 1024; i += 512) {
        const int row = i >> 4, kq = i & 15;
        int tk = tsk[row]; if (tk < 0) tk = 0;
        const int b = tk >> 6, tt = tk & 63;
        const size_t prow = (size_t)(b * 40 + 1 + tt) * 64 + 4 * kq;
        const size_t nrow = (size_t)(b * 39 + tt) * 64 + 4 * kq;
        float4 v;
        v = *(const float4*)&y[prow];
        GT[(4*kq+0)*68+row]=v.x; GT[(4*kq+1)*68+row]=v.y;
        GT[(4*kq+2)*68+row]=v.z; GT[(4*kq+3)*68+row]=v.w;
        v = *(const float4*)&ub[prow];
        XT[(4*kq+0)*68+row]=v.x; XT[(4*kq+1)*68+row]=v.y;
        XT[(4*kq+2)*68+row]=v.z; XT[(4*kq+3)*68+row]=v.w;
        v = *(const float4*)&nub[nrow];
        NT[(4*kq+0)*68+row]=v.x; NT[(4*kq+1)*68+row]=v.y;
        NT[(4*kq+2)*68+row]=v.z; NT[(4*kq+3)*68+row]=v.w;
    }
    __syncthreads();

    // layer 1: two j-passes of 64 cols; thread tile 2 rows x 4 cols
    #pragma unroll
    for (int pass = 0; pass < 2; ++pass) {
        const int j0 = 4 * tx + 64 * pass;
        unsigned long long ag[4] = {}, ax[4] = {}, an[4] = {};
        #pragma unroll 4
        for (int k = 0; k < 64; ++k) {
            const unsigned long long g2 = *(const unsigned long long*)&GT[k * 68 + 2 * ty];
            const unsigned long long x2 = *(const unsigned long long*)&XT[k * 68 + 2 * ty];
            const unsigned long long n2 = *(const unsigned long long*)&NT[k * 68 + 2 * ty];
            const float4 wa4 = *(const float4*)&W1s[k * 128 + j0];
            const float4 wb4 = *(const float4*)&W1s[(64 + k) * 128 + j0];
            const float wav[4] = {wa4.x, wa4.y, wa4.z, wa4.w};
            const float wbv[4] = {wb4.x, wb4.y, wb4.z, wb4.w};
            #pragma unroll
            for (int j = 0; j < 4; ++j) {
                unsigned long long w;
                w = dup2(wav[j]); fma2(ag[j], g2, w);
                w = dup2(wbv[j]); fma2(ax[j], x2, w); fma2(an[j], n2, w);
            }
        }
        #pragma unroll
        for (int j = 0; j < 4; ++j) {
            const float2 gv = unp(ag[j]);
            const float2 xv = unp(ax[j]);
            const float2 nv = unp(an[j]);
            const float bb = b1s[j0 + j];
            float2 o;
            o.x = fmaxf(gv.x + xv.x + bb, 0.0f);
            o.y = fmaxf(gv.y + xv.y + bb, 0.0f);
            *(float2*)&H1p[(j0 + j) * 68 + 2 * ty] = o;
            o.x = fmaxf(gv.x + nv.x + bb, 0.0f);
            o.y = fmaxf(gv.y + nv.y + bb, 0.0f);
            *(float2*)&H1n[(j0 + j) * 68 + 2 * ty] = o;
        }
    }
    __syncthreads();

    // layer 2 (k=128) + layer 3 + loss
    unsigned long long accp[4] = {}, accn[4] = {};
    #pragma unroll 4
    for (int k = 0; k < 128; ++k) {
        const unsigned long long hp2 = *(const unsigned long long*)&H1p[k * 68 + 2 * ty];
        const unsigned long long hn2 = *(const unsigned long long*)&H1n[k * 68 + 2 * ty];
        const float4 w4 = *(const float4*)&W2s[k * 64 + 4 * tx];
        const float wv[4] = {w4.x, w4.y, w4.z, w4.w};
        #pragma unroll
        for (int j = 0; j < 4; ++j) {
            const unsigned long long w = dup2(wv[j]);
            fma2(accp[j], hp2, w); fma2(accn[j], hn2, w);
        }
    }
    float sp[2] = {0, 0}, sn[2] = {0, 0};
    #pragma unroll
    for (int j = 0; j < 4; ++j) {
        const float2 pv = unp(accp[j]);
        const float2 nv = unp(accn[j]);
        const float bb = b2s[4 * tx + j], wv3 = w3s[4 * tx + j];
        sp[0] += fmaxf(pv.x + bb, 0.0f) * wv3;
        sp[1] += fmaxf(pv.y + bb, 0.0f) * wv3;
        sn[0] += fmaxf(nv.x + bb, 0.0f) * wv3;
        sn[1] += fmaxf(nv.y + bb, 0.0f) * wv3;
    }
    #pragma unroll
    for (int off = 1; off < 16; off <<= 1) {
        sp[0] += __shfl_xor_sync(0xffffffffu, sp[0], off);
        sp[1] += __shfl_xor_sync(0xffffffffu, sp[1], off);
        sn[0] += __shfl_xor_sync(0xffffffffu, sn[0], off);
        sn[1] += __shfl_xor_sync(0xffffffffu, sn[1], off);
    }
    if (tx == 0) {
        const float b3v = b3[0];
        const float loge = logf(1e-7f);
        const float log1me = logf(1.0f - 1e-7f);
        float accL = 0.0f;
        #pragma unroll
        for (int i = 0; i < 2; ++i) {
            const int row = 2 * ty + i;
            if (tsk[row] >= 0) {
                const float p  = sigf(sp[i] + b3v);
                const float pn = sigf(sn[i] + b3v);
                const float lp = -(p  * log1me + (1.0f - p)  * loge);
                const float ln = -(pn * loge  + (1.0f - pn) * log1me);
                accL += lp + ln;
            }
        }
        red[ty] = accL;
    }
    __syncthreads();
    if (tid == 0) {
        float L = 0.0f;
        #pragma unroll
        for (int i = 0; i < 32; ++i) L += red[i];
        g_partials[blockIdx.x] = L;
    }
}

// -------- deterministic final reduction --------
__global__ void fin_k(float* __restrict__ out, int out_size) {
    __shared__ float s[256];
    float L = 0.0f;
    for (int i = threadIdx.x; i < NTILES; i += 256) L += g_partials[i];
    s[threadIdx.x] = L; __syncthreads();
    for (int off = 128; off; off >>= 1) {
        if (threadIdx.x < off) s[threadIdx.x] += s[threadIdx.x + off];
        __syncthreads();
    }
    if (threadIdx.x == 0) {
        const float cnt = fmaxf((float)g_nm, 1.0f);
        out[out_size - 1] = s[0] / (2.0f * cnt);
    }
}

extern "C" void kernel_launch(void* const* d_in, const int* in_sizes, int n_in,
                              void* d_out, int out_size) {
    const float* ub    = (const float*)d_in[0];
    const void*  mask  = d_in[1];
    const float* nub   = (const float*)d_in[2];
    const void*  nmask = d_in[3];
    const float* W     = (const float*)d_in[4];
    const float* U     = (const float*)d_in[5];
    const float* bias  = (const float*)d_in[6];
    const float* w1    = (const float*)d_in[7];
    const float* b1    = (const float*)d_in[8];
    const float* w2    = (const float*)d_in[9];
    const float* b2    = (const float*)d_in[10];
    const float* w3    = (const float*)d_in[11];
    const float* b3    = (const float*)d_in[12];
    float* y = (float*)d_out;

    cudaFuncSetAttribute(xproj_k, cudaFuncAttributeMaxDynamicSharedMemorySize, XP_SMEM);
    cudaFuncSetAttribute(gru_k,   cudaFuncAttributeMaxDynamicSharedMemorySize, GRU_SMEM);
    cudaFuncSetAttribute(mlp_k,   cudaFuncAttributeMaxDynamicSharedMemorySize, MLP_SMEM);

    detect_k<<<1, 256>>>((const int*)mask);
    cnt_k<<<32, 256>>>(nmask);
    off_k<<<1, 256>>>();
    fill_k<<<32, 256>>>(nmask);
    xproj_k<<<1280, 256, XP_SMEM>>>(ub, W, bias);
    gru_k<<<128, 512, GRU_SMEM>>>(mask, U, bias, y);
    mlp_k<<<NTILES, 512, MLP_SMEM>>>(ub, nub, w1, b1, w2, b2, w3, b3, y);
    fin_k<<<1, 256>>>(y, out_size);
}

// round 7
// speedup vs baseline: 2.5213x; 1.3510x over previous
#include <cuda_runtime.h>
#include <cuda_bf16.h>
#include <math.h>

// Problem constants
#define Bn 8192
#define Tn 40
#define En 64
#define ROWS (Bn*Tn)              // 327680
#define NTILES 4992               // ceil(8192*39/64)
#define NMLP_CTAS 148

#define XP_SMEM  ((12288 + 64*68)*4)   // 66560 B
#define GRU_SMEM ((12288 + 2*64*66)*4) // 82944 B
#define MLP_SMEM (45952*4)             // 183808 B

// -------- device scratch (no allocations allowed) --------
__device__ float g_xproj[(size_t)ROWS * 192];   // 240 MB
__device__ int   g_maskMode;                    // 0=u8, 1=int32, 2=float32
__device__ float g_partials[NMLP_CTAS];
__device__ int   g_tasks[NTILES * 64];
__device__ int   g_cnt[Bn];
__device__ int   g_off[Bn];
__device__ int   g_nm;

__device__ __forceinline__ float mval(const void* m, int idx, int mode) {
    if (mode == 1) return ((const int*)m)[idx] ? 1.0f : 0.0f;
    if (mode == 2) return ((const float*)m)[idx];
    return ((const unsigned char*)m)[idx] ? 1.0f : 0.0f;
}
__device__ __forceinline__ float sigf(float v) { return 1.0f / (1.0f + __expf(-v)); }
__device__ __forceinline__ float tanhf_(float v) {
    return 1.0f - 2.0f / (__expf(2.0f * v) + 1.0f);
}

// packed f32x2 helpers
__device__ __forceinline__ unsigned long long dup2(float x) {
    unsigned long long r; unsigned u = __float_as_uint(x);
    asm("mov.b64 %0, {%1, %1};" : "=l"(r) : "r"(u));
    return r;
}
__device__ __forceinline__ void fma2(unsigned long long& d,
                                     unsigned long long a, unsigned long long b) {
    asm("fma.rn.f32x2 %0, %1, %2, %0;" : "+l"(d) : "l"(a), "l"(b));
}
__device__ __forceinline__ float2 unp(unsigned long long v) {
    unsigned lo, hi;
    asm("mov.b64 {%0, %1}, %2;" : "=r"(lo), "=r"(hi) : "l"(v));
    return make_float2(__uint_as_float(lo), __uint_as_float(hi));
}

// tf32 helpers
__device__ __forceinline__ unsigned tf32c(float x) {
    unsigned r; asm("cvt.rna.tf32.f32 %0, %1;" : "=r"(r) : "f"(x)); return r;
}
__device__ __forceinline__ void mma_tf32(float c[4], const uint4& a, const uint2& b) {
    asm("mma.sync.aligned.m16n8k8.row.col.f32.tf32.tf32.f32 "
        "{%0,%1,%2,%3}, {%4,%5,%6,%7}, {%8,%9}, {%0,%1,%2,%3};"
        : "+f"(c[0]), "+f"(c[1]), "+f"(c[2]), "+f"(c[3])
        : "r"(a.x), "r"(a.y), "r"(a.z), "r"(a.w), "r"(b.x), "r"(b.y));
}

// -------- mask dtype probe (reads only within smallest candidate buffer) --------
__global__ void detect_k(const int* __restrict__ m32) {
    __shared__ int sB, sF;
    if (threadIdx.x == 0) { sB = 1; sF = 1; }
    __syncthreads();
    int okB = 1, okF = 1;
    for (int i = threadIdx.x; i < 2560; i += blockDim.x) {
        int v = m32[i];
        okB = okB && (v == 0 || v == 1);
        okF = okF && (v == 0 || v == 0x3F800000);
    }
    atomicAnd(&sB, okB);
    atomicAnd(&sF, okF);
    __syncthreads();
    if (threadIdx.x == 0) g_maskMode = sB ? 1 : (sF ? 2 : 0);
}

// -------- per-row valid-count --------
__global__ void cnt_k(const void* __restrict__ nmask) {
    const int b = blockIdx.x * 256 + threadIdx.x;
    const int mode = g_maskMode;
    int c = 0;
    #pragma unroll
    for (int tt = 0; tt < 39; ++tt)
        c += (mval(nmask, b * 39 + tt, mode) != 0.0f);
    g_cnt[b] = c;
}

// -------- exclusive offsets + tail padding (deterministic) --------
__global__ void off_k() {
    __shared__ int ssum[256];
    const int tid = threadIdx.x;
    int c[32]; int tot = 0;
    #pragma unroll
    for (int r = 0; r < 32; ++r) { c[r] = g_cnt[tid * 32 + r]; tot += c[r]; }
    ssum[tid] = tot; __syncthreads();
    for (int off = 1; off < 256; off <<= 1) {
        int v = (tid >= off) ? ssum[tid - off] : 0;
        __syncthreads();
        ssum[tid] += v;
        __syncthreads();
    }
    int base = ssum[tid] - tot;
    #pragma unroll
    for (int r = 0; r < 32; ++r) { g_off[tid * 32 + r] = base; base += c[r]; }
    const int total = ssum[255];
    const int padded = ((total + 63) >> 6) << 6;
    for (int i = total + tid; i < padded; i += 256) g_tasks[i] = -1;
    if (tid == 0) g_nm = total;
}

// -------- fill compacted task list --------
__global__ void fill_k(const void* __restrict__ nmask) {
    const int b = blockIdx.x * 256 + threadIdx.x;
    const int mode = g_maskMode;
    int off = g_off[b];
    #pragma unroll
    for (int tt = 0; tt < 39; ++tt)
        if (mval(nmask, b * 39 + tt, mode) != 0.0f) g_tasks[off++] = (b << 6) | tt;
}

// -------- xproj = x @ W + bi  (M=327680, K=64, N=192), FFMA2 core --------
__global__ void __launch_bounds__(256, 2) xproj_k(
    const float* __restrict__ x, const float* __restrict__ W,
    const float* __restrict__ bias)
{
    extern __shared__ float sm[];
    float* Ws = sm;            // 64*192
    float* XT = sm + 12288;    // [k][row pitch 68]

    const int tid = threadIdx.x;
    for (int i = tid; i < 3072; i += 256)
        ((float4*)Ws)[i] = ((const float4*)W)[i];

    const int tx = tid & 15, ty = tid >> 4;
    const float4 ba = *(const float4*)&bias[4 * tx];
    const float4 bb = *(const float4*)&bias[64 + 4 * tx];
    const float4 bc = *(const float4*)&bias[128 + 4 * tx];
    const float bav[4] = {ba.x, ba.y, ba.z, ba.w};
    const float bbv[4] = {bb.x, bb.y, bb.z, bb.w};
    const float bcv[4] = {bc.x, bc.y, bc.z, bc.w};

    for (int tile = 0; tile < 4; ++tile) {
        const int r0 = (blockIdx.x * 4 + tile) * 64;
        __syncthreads();
        for (int i = tid; i < 1024; i += 256) {
            const int row = i >> 4, kq = i & 15;
            const float4 v = *(const float4*)&x[(size_t)(r0 + row) * 64 + 4 * kq];
            XT[(4 * kq + 0) * 68 + row] = v.x;
            XT[(4 * kq + 1) * 68 + row] = v.y;
            XT[(4 * kq + 2) * 68 + row] = v.z;
            XT[(4 * kq + 3) * 68 + row] = v.w;
        }
        __syncthreads();

        unsigned long long az[4][2] = {}, ar2[4][2] = {}, ah[4][2] = {};
        #pragma unroll 8
        for (int k = 0; k < 64; ++k) {
            const float4 hv4 = *(const float4*)&XT[k * 68 + 4 * ty];
            const float hvv[4] = {hv4.x, hv4.y, hv4.z, hv4.w};
            const ulonglong2 wz = *(const ulonglong2*)&Ws[k * 192 + 4 * tx];
            const ulonglong2 wr = *(const ulonglong2*)&Ws[k * 192 + 64 + 4 * tx];
            const ulonglong2 wh = *(const ulonglong2*)&Ws[k * 192 + 128 + 4 * tx];
            #pragma unroll
            for (int i = 0; i < 4; ++i) {
                const unsigned long long d = dup2(hvv[i]);
                fma2(az[i][0], d, wz.x);  fma2(az[i][1], d, wz.y);
                fma2(ar2[i][0], d, wr.x); fma2(ar2[i][1], d, wr.y);
                fma2(ah[i][0], d, wh.x);  fma2(ah[i][1], d, wh.y);
            }
        }
        #pragma unroll
        for (int i = 0; i < 4; ++i) {
            const size_t base = (size_t)(r0 + 4 * ty + i) * 192;
            float2 v0, v1;
            float4 o;
            v0 = unp(az[i][0]); v1 = unp(az[i][1]);
            o.x = v0.x + bav[0]; o.y = v0.y + bav[1];
            o.z = v1.x + bav[2]; o.w = v1.y + bav[3];
            *(float4*)&g_xproj[base + 4 * tx] = o;
            v0 = unp(ar2[i][0]); v1 = unp(ar2[i][1]);
            o.x = v0.x + bbv[0]; o.y = v0.y + bbv[1];
            o.z = v1.x + bbv[2]; o.w = v1.y + bbv[3];
            *(float4*)&g_xproj[base + 64 + 4 * tx] = o;
            v0 = unp(ah[i][0]); v1 = unp(ah[i][1]);
            o.x = v0.x + bcv[0]; o.y = v0.y + bcv[1];
            o.z = v1.x + bcv[2]; o.w = v1.y + bcv[3];
            *(float4*)&g_xproj[base + 128 + 4 * tx] = o;
        }
    }
}

// -------- GRU: 128 CTAs x 64 rows x 512 threads, double-buffered H --------
__global__ void __launch_bounds__(512, 1) gru_k(
    const void* __restrict__ mask, const float* __restrict__ U,
    const float* __restrict__ bias, float* __restrict__ y)
{
    extern __shared__ float sm[];
    float* Us = sm;              // 12288
    float* Ha = sm + 12288;      // 64*66
    float* Hb = Ha + 4224;       // 64*66

    const int tid = threadIdx.x, tx = tid & 15, ty = tid >> 4;  // ty 0..31
    for (int i = tid; i < 3072; i += 512)
        ((float4*)Us)[i] = ((const float4*)U)[i];
    for (int i = tid; i < 4224; i += 512) Ha[i] = 0.0f;

    const float4 bz4 = *(const float4*)&bias[192 + 4 * tx];
    const float4 br4 = *(const float4*)&bias[192 + 64 + 4 * tx];
    const float4 bh4 = *(const float4*)&bias[192 + 128 + 4 * tx];
    const float bz[4] = {bz4.x, bz4.y, bz4.z, bz4.w};
    const float br[4] = {br4.x, br4.y, br4.z, br4.w};
    const float bh[4] = {bh4.x, bh4.y, bh4.z, bh4.w};

    const int mode = g_maskMode;
    const int r0 = blockIdx.x * 64 + 2 * ty;   // this thread's row pair
    __syncthreads();

    float* Hr = Ha;
    float* Hw = Hb;
    for (int t = 0; t < Tn; ++t) {
        float4 xzp[2], xrp[2], xhp[2]; float mv[2];
        #pragma unroll
        for (int i = 0; i < 2; ++i) {
            const size_t xb = (size_t)((r0 + i) * Tn + t) * 192;
            xzp[i] = *(const float4*)&g_xproj[xb + 4 * tx];
            xrp[i] = *(const float4*)&g_xproj[xb + 64 + 4 * tx];
            xhp[i] = *(const float4*)&g_xproj[xb + 128 + 4 * tx];
            mv[i]  = mval(mask, (r0 + i) * Tn + t, mode);
        }

        unsigned long long az[2][2] = {}, ar2[2][2] = {}, ah[2][2] = {};
        #pragma unroll 8
        for (int k = 0; k < 64; ++k) {
            const float2 hv = *(const float2*)&Hr[k * 66 + 2 * ty];
            const unsigned long long d0 = dup2(hv.x), d1 = dup2(hv.y);
            const ulonglong2 wz = *(const ulonglong2*)&Us[k * 192 + 4 * tx];
            const ulonglong2 wr = *(const ulonglong2*)&Us[k * 192 + 64 + 4 * tx];
            const ulonglong2 wh = *(const ulonglong2*)&Us[k * 192 + 128 + 4 * tx];
            fma2(az[0][0], d0, wz.x);  fma2(az[0][1], d0, wz.y);
            fma2(az[1][0], d1, wz.x);  fma2(az[1][1], d1, wz.y);
            fma2(ar2[0][0], d0, wr.x); fma2(ar2[0][1], d0, wr.y);
            fma2(ar2[1][0], d1, wr.x); fma2(ar2[1][1], d1, wr.y);
            fma2(ah[0][0], d0, wh.x);  fma2(ah[0][1], d0, wh.y);
            fma2(ah[1][0], d1, wh.x);  fma2(ah[1][1], d1, wh.y);
        }

        #pragma unroll
        for (int i = 0; i < 2; ++i) {
            float aZ[4], aR[4], aH[4];
            { float2 v = unp(az[i][0]);  aZ[0] = v.x; aZ[1] = v.y;
              v = unp(az[i][1]);         aZ[2] = v.x; aZ[3] = v.y;
              v = unp(ar2[i][0]);        aR[0] = v.x; aR[1] = v.y;
              v = unp(ar2[i][1]);        aR[2] = v.x; aR[3] = v.y;
              v = unp(ah[i][0]);         aH[0] = v.x; aH[1] = v.y;
              v = unp(ah[i][1]);         aH[2] = v.x; aH[3] = v.y; }
            const float xzv[4] = {xzp[i].x, xzp[i].y, xzp[i].z, xzp[i].w};
            const float xrv[4] = {xrp[i].x, xrp[i].y, xrp[i].z, xrp[i].w};
            const float xhv[4] = {xhp[i].x, xhp[i].y, xhp[i].z, xhp[i].w};
            float hnew[4];
            #pragma unroll
            for (int jj = 0; jj < 4; ++jj) {
                const float ho = Hr[(4 * tx + jj) * 66 + 2 * ty + i];
                const float z = sigf(xzv[jj] + bz[jj] + aZ[jj]);
                const float r = sigf(xrv[jj] + br[jj] + aR[jj]);
                const float hh = tanhf_(xhv[jj] + bh[jj] + r * aH[jj]);
                const float hn = z * ho + (1.0f - z) * hh;
                hnew[jj] = (mv[i] != 0.0f) ? hn : ho;
                Hw[(4 * tx + jj) * 66 + 2 * ty + i] = hnew[jj];
            }
            float4 o; o.x = hnew[0]; o.y = hnew[1]; o.z = hnew[2]; o.w = hnew[3];
            *(float4*)&y[(size_t)((r0 + i) * Tn + t) * 64 + 4 * tx] = o;
        }
        __syncthreads();
        float* tp = Hr; Hr = Hw; Hw = tp;
    }
}

// -------- MLP via tf32 mma.sync: persistent CTAs, fragment-order smem --------
// smem float offsets
#define O_W1F  0        // 16*16*32*2 = 16384  B-frags layer1 (k0..127 x j0..127)
#define O_W2F  16384    // 16*8*32*2  = 8192   B-frags layer2
#define O_AFG  24576    // 4*8*32*4   = 4096   A-frags G
#define O_AFX  28672    // 4096 A-frags X
#define O_AFN  32768    // 4096 A-frags N
#define O_H1F  36864    // 4*16*32*4  = 8192   A-frags H1 (reused pos/neg)
#define O_PP   45056    // 256 partP
#define O_PN   45312    // 256 partN
#define O_B1   45568    // 128
#define O_B2   45696    // 64
#define O_W3   45760    // 64
#define O_RED  45824    // 64
#define O_TSK  45888    // 64 ints
// total 45952

__device__ __forceinline__ int afidx(int row, int k) {
    // A fragment position for m16n8k8 tf32: tile (mt=row/16, ks=k/8)
    const int mt = row >> 4, ks = k >> 3;
    const int lane = ((row & 7) << 2) | (k & 3);
    const int slot = ((row >> 3) & 1) + (((k >> 2) & 1) << 1);
    return (((mt << 3) + ks) << 5 | lane) * 4 + slot;
}
__device__ __forceinline__ int h1idx(int row, int j) {
    // H1 A-frag layout: [mt][ks2=j/8][lane][slot], 16 ksteps
    const int mt = row >> 4, ks = j >> 3;
    const int lane = ((row & 7) << 2) | (j & 3);
    const int slot = ((row >> 3) & 1) + (((j >> 2) & 1) << 1);
    return (((mt << 4) + ks) << 5 | lane) * 4 + slot;
}

__global__ void __launch_bounds__(512, 1) mlp_k(
    const float* __restrict__ ub, const float* __restrict__ nub,
    const float* __restrict__ w1, const float* __restrict__ b1,
    const float* __restrict__ w2, const float* __restrict__ b2,
    const float* __restrict__ w3, const float* __restrict__ b3,
    const float* __restrict__ y)
{
    extern __shared__ float sm[];
    unsigned* W1F = (unsigned*)(sm + O_W1F);
    unsigned* W2F = (unsigned*)(sm + O_W2F);
    unsigned* AFG = (unsigned*)(sm + O_AFG);
    unsigned* AFX = (unsigned*)(sm + O_AFX);
    unsigned* AFN = (unsigned*)(sm + O_AFN);
    unsigned* H1F = (unsigned*)(sm + O_H1F);
    float* partP = sm + O_PP;
    float* partN = sm + O_PN;
    float* b1s = sm + O_B1;
    float* b2s = sm + O_B2;
    float* w3s = sm + O_W3;
    float* red = sm + O_RED;
    int*   tsk = (int*)(sm + O_TSK);

    const int tid = threadIdx.x, lane = tid & 31, w = tid >> 5;
    const int g = lane >> 2, tig = lane & 3;
    const int mt = w & 3, ng = w >> 2;   // warp tile coords

    // one-time: permute weights into fragment order (tf32)
    for (int idx = tid; idx < 16 * 16 * 32; idx += 512) {
        const int l = idx & 31, nt = (idx >> 5) & 15, ks = idx >> 9;
        const int gg = l >> 2, tg = l & 3;
        W1F[idx * 2]     = tf32c(w1[(ks * 8 + tg) * 128 + nt * 8 + gg]);
        W1F[idx * 2 + 1] = tf32c(w1[(ks * 8 + tg + 4) * 128 + nt * 8 + gg]);
    }
    for (int idx = tid; idx < 16 * 8 * 32; idx += 512) {
        const int l = idx & 31, nt = (idx >> 5) & 7, ks = idx >> 8;
        const int gg = l >> 2, tg = l & 3;
        W2F[idx * 2]     = tf32c(w2[(ks * 8 + tg) * 64 + nt * 8 + gg]);
        W2F[idx * 2 + 1] = tf32c(w2[(ks * 8 + tg + 4) * 64 + nt * 8 + gg]);
    }
    if (tid < 128) b1s[tid] = b1[tid];
    if (tid >= 128 && tid < 192) b2s[tid - 128] = b2[tid - 128];
    if (tid >= 192 && tid < 256) w3s[tid - 192] = w3[tid - 192];

    const float b3v = b3[0];
    const float loge = logf(1e-7f);
    const float log1me = logf(1.0f - 1e-7f);
    const int nm = g_nm;
    const int ntiles = (nm + 63) >> 6;
    float accL = 0.0f;

    for (int tile = blockIdx.x; tile < ntiles; tile += NMLP_CTAS) {
        __syncthreads();   // protect tsk/smem reuse from previous iter
        if (tid < 64) tsk[tid] = g_tasks[tile * 64 + tid];
        __syncthreads();

        // gather + tf32-convert into fragment-order A tiles
        for (int i = tid; i < 1024; i += 512) {
            const int row = i >> 4, kq = i & 15, k0 = kq * 4;
            int tk = tsk[row]; if (tk < 0) tk = 0;
            const int b = tk >> 6, tt = tk & 63;
            const size_t prow = (size_t)(b * 40 + 1 + tt) * 64 + k0;
            const size_t nrow = (size_t)(b * 39 + tt) * 64 + k0;
            float4 v;
            v = *(const float4*)&y[prow];
            AFG[afidx(row, k0)]     = tf32c(v.x);
            AFG[afidx(row, k0 + 1)] = tf32c(v.y);
            AFG[afidx(row, k0 + 2)] = tf32c(v.z);
            AFG[afidx(row, k0 + 3)] = tf32c(v.w);
            v = *(const float4*)&ub[prow];
            AFX[afidx(row, k0)]     = tf32c(v.x);
            AFX[afidx(row, k0 + 1)] = tf32c(v.y);
            AFX[afidx(row, k0 + 2)] = tf32c(v.z);
            AFX[afidx(row, k0 + 3)] = tf32c(v.w);
            v = *(const float4*)&nub[nrow];
            AFN[afidx(row, k0)]     = tf32c(v.x);
            AFN[afidx(row, k0 + 1)] = tf32c(v.y);
            AFN[afidx(row, k0 + 2)] = tf32c(v.z);
            AFN[afidx(row, k0 + 3)] = tf32c(v.w);
        }
        __syncthreads();

        // shared G @ W1a
        float cg[4][4] = {};
        #pragma unroll
        for (int ks = 0; ks < 8; ++ks) {
            const uint4 a = ((const uint4*)AFG)[(mt * 8 + ks) * 32 + lane];
            #pragma unroll
            for (int i = 0; i < 4; ++i) {
                const int nt = ng * 4 + i;
                const uint2 b = ((const uint2*)W1F)[(ks * 16 + nt) * 32 + lane];
                mma_tf32(cg[i], a, b);
            }
        }

        // ---------- positive branch ----------
        {
            float cp[4][4];
            #pragma unroll
            for (int i = 0; i < 4; ++i)
                #pragma unroll
                for (int q = 0; q < 4; ++q) cp[i][q] = cg[i][q];
            #pragma unroll
            for (int ks = 0; ks < 8; ++ks) {
                const uint4 a = ((const uint4*)AFX)[(mt * 8 + ks) * 32 + lane];
                #pragma unroll
                for (int i = 0; i < 4; ++i) {
                    const int nt = ng * 4 + i;
                    const uint2 b = ((const uint2*)W1F)[((ks + 8) * 16 + nt) * 32 + lane];
                    mma_tf32(cp[i], a, b);
                }
            }
            const int row1 = mt * 16 + g;
            #pragma unroll
            for (int i = 0; i < 4; ++i) {
                const int j0 = (ng * 4 + i) * 8 + 2 * tig;
                H1F[h1idx(row1, j0)]         = tf32c(fmaxf(cp[i][0] + b1s[j0], 0.0f));
                H1F[h1idx(row1, j0 + 1)]     = tf32c(fmaxf(cp[i][1] + b1s[j0 + 1], 0.0f));
                H1F[h1idx(row1 + 8, j0)]     = tf32c(fmaxf(cp[i][2] + b1s[j0], 0.0f));
                H1F[h1idx(row1 + 8, j0 + 1)] = tf32c(fmaxf(cp[i][3] + b1s[j0 + 1], 0.0f));
            }
        }
        __syncthreads();
        {
            float c2[2][4] = {};
            #pragma unroll
            for (int ks = 0; ks < 16; ++ks) {
                const uint4 a = ((const uint4*)H1F)[(mt * 16 + ks) * 32 + lane];
                #pragma unroll
                for (int i = 0; i < 2; ++i) {
                    const int nt = ng * 2 + i;
                    const uint2 b = ((const uint2*)W2F)[(ks * 8 + nt) * 32 + lane];
                    mma_tf32(c2[i], a, b);
                }
            }
            float s1 = 0.0f, s2 = 0.0f;
            #pragma unroll
            for (int i = 0; i < 2; ++i) {
                const int j0 = (ng * 2 + i) * 8 + 2 * tig;
                s1 += fmaxf(c2[i][0] + b2s[j0], 0.0f) * w3s[j0]
                    + fmaxf(c2[i][1] + b2s[j0 + 1], 0.0f) * w3s[j0 + 1];
                s2 += fmaxf(c2[i][2] + b2s[j0], 0.0f) * w3s[j0]
                    + fmaxf(c2[i][3] + b2s[j0 + 1], 0.0f) * w3s[j0 + 1];
            }
            s1 += __shfl_xor_sync(0xffffffffu, s1, 1);
            s1 += __shfl_xor_sync(0xffffffffu, s1, 2);
            s2 += __shfl_xor_sync(0xffffffffu, s2, 1);
            s2 += __shfl_xor_sync(0xffffffffu, s2, 2);
            if (tig == 0) {
                partP[ng * 64 + mt * 16 + g] = s1;
                partP[ng * 64 + mt * 16 + 8 + g] = s2;
            }
        }
        __syncthreads();   // H1F reuse + partP complete

        // ---------- negative branch ----------
        {
            float cn[4][4];
            #pragma unroll
            for (int i = 0; i < 4; ++i)
                #pragma unroll
                for (int q = 0; q < 4; ++q) cn[i][q] = cg[i][q];
            #pragma unroll
            for (int ks = 0; ks < 8; ++ks) {
                const uint4 a = ((const uint4*)AFN)[(mt * 8 + ks) * 32 + lane];
                #pragma unroll
                for (int i = 0; i < 4; ++i) {
                    const int nt = ng * 4 + i;
                    const uint2 b = ((const uint2*)W1F)[((ks + 8) * 16 + nt) * 32 + lane];
                    mma_tf32(cn[i], a, b);
                }
            }
            const int row1 = mt * 16 + g;
            #pragma unroll
            for (int i = 0; i < 4; ++i) {
                const int j0 = (ng * 4 + i) * 8 + 2 * tig;
                H1F[h1idx(row1, j0)]         = tf32c(fmaxf(cn[i][0] + b1s[j0], 0.0f));
                H1F[h1idx(row1, j0 + 1)]     = tf32c(fmaxf(cn[i][1] + b1s[j0 + 1], 0.0f));
                H1F[h1idx(row1 + 8, j0)]     = tf32c(fmaxf(cn[i][2] + b1s[j0], 0.0f));
                H1F[h1idx(row1 + 8, j0 + 1)] = tf32c(fmaxf(cn[i][3] + b1s[j0 + 1], 0.0f));
            }
        }
        __syncthreads();
        {
            float c2[2][4] = {};
            #pragma unroll
            for (int ks = 0; ks < 16; ++ks) {
                const uint4 a = ((const uint4*)H1F)[(mt * 16 + ks) * 32 + lane];
                #pragma unroll
                for (int i = 0; i < 2; ++i) {
                    const int nt = ng * 2 + i;
                    const uint2 b = ((const uint2*)W2F)[(ks * 8 + nt) * 32 + lane];
                    mma_tf32(c2[i], a, b);
                }
            }
            float s1 = 0.0f, s2 = 0.0f;
            #pragma unroll
            for (int i = 0; i < 2; ++i) {
                const int j0 = (ng * 2 + i) * 8 + 2 * tig;
                s1 += fmaxf(c2[i][0] + b2s[j0], 0.0f) * w3s[j0]
                    + fmaxf(c2[i][1] + b2s[j0 + 1], 0.0f) * w3s[j0 + 1];
                s2 += fmaxf(c2[i][2] + b2s[j0], 0.0f) * w3s[j0]
                    + fmaxf(c2[i][3] + b2s[j0 + 1], 0.0f) * w3s[j0 + 1];
            }
            s1 += __shfl_xor_sync(0xffffffffu, s1, 1);
            s1 += __shfl_xor_sync(0xffffffffu, s1, 2);
            s2 += __shfl_xor_sync(0xffffffffu, s2, 1);
            s2 += __shfl_xor_sync(0xffffffffu, s2, 2);
            if (tig == 0) {
                partN[ng * 64 + mt * 16 + g] = s1;
                partN[ng * 64 + mt * 16 + 8 + g] = s2;
            }
        }
        __syncthreads();

        // ---------- loss for this tile ----------
        if (tid < 64 && tsk[tid] >= 0) {
            const float lp_ = partP[tid] + partP[64 + tid] + partP[128 + tid]
                            + partP[192 + tid] + b3v;
            const float ln_ = partN[tid] + partN[64 + tid] + partN[128 + tid]
                            + partN[192 + tid] + b3v;
            const float p  = sigf(lp_);
            const float pn = sigf(ln_);
            accL += -(p  * log1me + (1.0f - p)  * loge)
                    - (pn * loge  + (1.0f - pn) * log1me);
        }
    }

    // block reduction of accL (deterministic)
    __syncthreads();
    if (tid < 64) red[tid] = 0.0f;
    __syncthreads();
    // fold 512 threads into 64 fixed slots in fixed order
    for (int grp = 0; grp < 8; ++grp) {
        if ((tid >> 6) == grp) red[tid & 63] += accL;
        __syncthreads();
    }
    if (tid == 0) {
        float L = 0.0f;
        for (int i = 0; i < 64; ++i) L += red[i];
        g_partials[blockIdx.x] = L;
    }
}

// -------- deterministic final reduction --------
__global__ void fin_k(float* __restrict__ out, int out_size) {
    __shared__ float s[256];
    float L = 0.0f;
    for (int i = threadIdx.x; i < NMLP_CTAS; i += 256) L += g_partials[i];
    s[threadIdx.x] = L; __syncthreads();
    for (int off = 128; off; off >>= 1) {
        if (threadIdx.x < off) s[threadIdx.x] += s[threadIdx.x + off];
        __syncthreads();
    }
    if (threadIdx.x == 0) {
        const float cnt = fmaxf((float)g_nm, 1.0f);
        out[out_size - 1] = s[0] / (2.0f * cnt);
    }
}

extern "C" void kernel_launch(void* const* d_in, const int* in_sizes, int n_in,
                              void* d_out, int out_size) {
    const float* ub    = (const float*)d_in[0];
    const void*  mask  = d_in[1];
    const float* nub   = (const float*)d_in[2];
    const void*  nmask = d_in[3];
    const float* W     = (const float*)d_in[4];
    const float* U     = (const float*)d_in[5];
    const float* bias  = (const float*)d_in[6];
    const float* w1    = (const float*)d_in[7];
    const float* b1    = (const float*)d_in[8];
    const float* w2    = (const float*)d_in[9];
    const float* b2    = (const float*)d_in[10];
    const float* w3    = (const float*)d_in[11];
    const float* b3    = (const float*)d_in[12];
    float* y = (float*)d_out;

    cudaFuncSetAttribute(xproj_k, cudaFuncAttributeMaxDynamicSharedMemorySize, XP_SMEM);
    cudaFuncSetAttribute(gru_k,   cudaFuncAttributeMaxDynamicSharedMemorySize, GRU_SMEM);
    cudaFuncSetAttribute(mlp_k,   cudaFuncAttributeMaxDynamicSharedMemorySize, MLP_SMEM);

    detect_k<<<1, 256>>>((const int*)mask);
    cnt_k<<<32, 256>>>(nmask);
    off_k<<<1, 256>>>();
    fill_k<<<32, 256>>>(nmask);
    xproj_k<<<1280, 256, XP_SMEM>>>(ub, W, bias);
    gru_k<<<128, 512, GRU_SMEM>>>(mask, U, bias, y);
    mlp_k<<<NMLP_CTAS, 512, MLP_SMEM>>>(ub, nub, w1, b1, w2, b2, w3, b3, y);
    fin_k<<<1, 256>>>(y, out_size);
}

// round 9
// speedup vs baseline: 2.9332x; 1.1634x over previous
#include <cuda_runtime.h>
#include <cuda_bf16.h>
#include <math.h>

// Problem constants
#define Bn 8192
#define Tn 40
#define En 64
#define NTILES 4992               // ceil(8192*39/64)
#define NMLP_CTAS 148

#define FUSED_SMEM ((24576 + 4*4224)*4)   // 165888 B
#define MLP_SMEM (45952*4)                // 183808 B

// -------- device scratch (no allocations allowed) --------
__device__ int   g_maskMode;              // 0=u8, 1=int32, 2=float32
__device__ float g_partials[NMLP_CTAS];
__device__ int   g_tasks[NTILES * 64];
__device__ int   g_cnt[Bn];
__device__ int   g_off[Bn];
__device__ int   g_nm;

__device__ __forceinline__ float mval(const void* m, int idx, int mode) {
    if (mode == 1) return ((const int*)m)[idx] ? 1.0f : 0.0f;
    if (mode == 2) return ((const float*)m)[idx];
    return ((const unsigned char*)m)[idx] ? 1.0f : 0.0f;
}
__device__ __forceinline__ float sigf(float v) { return 1.0f / (1.0f + __expf(-v)); }
__device__ __forceinline__ float tanhf_(float v) {
    return 1.0f - 2.0f / (__expf(2.0f * v) + 1.0f);
}

// packed f32x2 helpers
__device__ __forceinline__ unsigned long long dup2(float x) {
    unsigned long long r; unsigned u = __float_as_uint(x);
    asm("mov.b64 %0, {%1, %1};" : "=l"(r) : "r"(u));
    return r;
}
__device__ __forceinline__ unsigned long long pack2(float a, float b) {
    unsigned long long r;
    asm("mov.b64 %0, {%1, %2};" : "=l"(r)
        : "r"(__float_as_uint(a)), "r"(__float_as_uint(b)));
    return r;
}
__device__ __forceinline__ void fma2(unsigned long long& d,
                                     unsigned long long a, unsigned long long b) {
    asm("fma.rn.f32x2 %0, %1, %2, %0;" : "+l"(d) : "l"(a), "l"(b));
}
__device__ __forceinline__ float2 unp(unsigned long long v) {
    unsigned lo, hi;
    asm("mov.b64 {%0, %1}, %2;" : "=r"(lo), "=r"(hi) : "l"(v));
    return make_float2(__uint_as_float(lo), __uint_as_float(hi));
}

// tf32 helpers
__device__ __forceinline__ unsigned tf32c(float x) {
    unsigned r; asm("cvt.rna.tf32.f32 %0, %1;" : "=r"(r) : "f"(x)); return r;
}
__device__ __forceinline__ void mma_tf32(float c[4], const uint4& a, const uint2& b) {
    asm("mma.sync.aligned.m16n8k8.row.col.f32.tf32.tf32.f32 "
        "{%0,%1,%2,%3}, {%4,%5,%6,%7}, {%8,%9}, {%0,%1,%2,%3};"
        : "+f"(c[0]), "+f"(c[1]), "+f"(c[2]), "+f"(c[3])
        : "r"(a.x), "r"(a.y), "r"(a.z), "r"(a.w), "r"(b.x), "r"(b.y));
}

// -------- mask dtype probe (reads only within smallest candidate buffer) --------
__global__ void detect_k(const int* __restrict__ m32) {
    __shared__ int sB, sF;
    if (threadIdx.x == 0) { sB = 1; sF = 1; }
    __syncthreads();
    int okB = 1, okF = 1;
    for (int i = threadIdx.x; i < 2560; i += blockDim.x) {
        int v = m32[i];
        okB = okB && (v == 0 || v == 1);
        okF = okF && (v == 0 || v == 0x3F800000);
    }
    atomicAnd(&sB, okB);
    atomicAnd(&sF, okF);
    __syncthreads();
    if (threadIdx.x == 0) g_maskMode = sB ? 1 : (sF ? 2 : 0);
}

// -------- per-row valid-count --------
__global__ void cnt_k(const void* __restrict__ nmask) {
    const int b = blockIdx.x * 256 + threadIdx.x;
    const int mode = g_maskMode;
    int c = 0;
    #pragma unroll
    for (int tt = 0; tt < 39; ++tt)
        c += (mval(nmask, b * 39 + tt, mode) != 0.0f);
    g_cnt[b] = c;
}

// -------- exclusive offsets + tail padding (deterministic) --------
__global__ void off_k() {
    __shared__ int ssum[256];
    const int tid = threadIdx.x;
    int c[32]; int tot = 0;
    #pragma unroll
    for (int r = 0; r < 32; ++r) { c[r] = g_cnt[tid * 32 + r]; tot += c[r]; }
    ssum[tid] = tot; __syncthreads();
    for (int off = 1; off < 256; off <<= 1) {
        int v = (tid >= off) ? ssum[tid - off] : 0;
        __syncthreads();
        ssum[tid] += v;
        __syncthreads();
    }
    int base = ssum[tid] - tot;
    #pragma unroll
    for (int r = 0; r < 32; ++r) { g_off[tid * 32 + r] = base; base += c[r]; }
    const int total = ssum[255];
    const int padded = ((total + 63) >> 6) << 6;
    for (int i = total + tid; i < padded; i += 256) g_tasks[i] = -1;
    if (tid == 0) g_nm = total;
}

// -------- fill compacted task list --------
__global__ void fill_k(const void* __restrict__ nmask) {
    const int b = blockIdx.x * 256 + threadIdx.x;
    const int mode = g_maskMode;
    int off = g_off[b];
    #pragma unroll
    for (int tt = 0; tt < 39; ++tt)
        if (mval(nmask, b * 39 + tt, mode) != 0.0f) g_tasks[off++] = (b << 6) | tt;
}

// -------- fused xproj + GRU recurrence --------
// 128 CTAs x 64 batch rows x 512 threads. Warp w owns output cols 4w..4w+3
// of each gate section (weight LDS are full-warp broadcasts). Lane owns rows
// (2*lane, 2*lane+1). z/r accumulators are shared between x@W and h@U
// (biases folded into accumulator init); only the h-candidate needs split
// accumulators. H and X double-buffered, one barrier per step, X for t+1
// prefetched via LDG at the top of step t.
__global__ void __launch_bounds__(512, 1) gruf_k(
    const float* __restrict__ x, const void* __restrict__ mask,
    const float* __restrict__ W, const float* __restrict__ U,
    const float* __restrict__ bias, float* __restrict__ y)
{
    extern __shared__ float sm[];
    float* Ws = sm;              // 12288  [k][192]
    float* Us = sm + 12288;      // 12288
    float* Ha = sm + 24576;      // [k=64][row pitch 66]
    float* Hb = Ha + 4224;
    float* Xa = Hb + 4224;
    float* Xb = Xa + 4224;

    const int tid = threadIdx.x, lane = tid & 31, w = tid >> 5;
    const int c0 = 4 * w;
    const int b0 = blockIdx.x * 64;
    const int mode = g_maskMode;

    for (int i = tid; i < 3072; i += 512) {
        ((float4*)Ws)[i] = ((const float4*)W)[i];
        ((float4*)Us)[i] = ((const float4*)U)[i];
    }
    for (int i = tid; i < 4224; i += 512) Ha[i] = 0.0f;

    // stage X for t=0: item i -> row i>>4, quad i&15
    #pragma unroll
    for (int rep = 0; rep < 2; ++rep) {
        const int i = tid + rep * 512;
        const int row = i >> 4, kq = i & 15;
        const float4 v = *(const float4*)&x[(size_t)((b0 + row) * Tn + 0) * 64 + 4 * kq];
        Xa[(4 * kq + 0) * 66 + row] = v.x;
        Xa[(4 * kq + 1) * 66 + row] = v.y;
        Xa[(4 * kq + 2) * 66 + row] = v.z;
        Xa[(4 * kq + 3) * 66 + row] = v.w;
    }

    // packed bias inits (per column pair); z/r fold input+recurrent biases
    const unsigned long long bzP0 = pack2(bias[c0] + bias[192 + c0],
                                          bias[c0 + 1] + bias[192 + c0 + 1]);
    const unsigned long long bzP1 = pack2(bias[c0 + 2] + bias[192 + c0 + 2],
                                          bias[c0 + 3] + bias[192 + c0 + 3]);
    const unsigned long long brP0 = pack2(bias[64 + c0] + bias[256 + c0],
                                          bias[64 + c0 + 1] + bias[256 + c0 + 1]);
    const unsigned long long brP1 = pack2(bias[64 + c0 + 2] + bias[256 + c0 + 2],
                                          bias[64 + c0 + 3] + bias[256 + c0 + 3]);
    const unsigned long long bxP0 = pack2(bias[128 + c0], bias[128 + c0 + 1]);
    const unsigned long long bxP1 = pack2(bias[128 + c0 + 2], bias[128 + c0 + 3]);
    const unsigned long long bhP0 = pack2(bias[320 + c0], bias[320 + c0 + 1]);
    const unsigned long long bhP1 = pack2(bias[320 + c0 + 2], bias[320 + c0 + 3]);

    const int r0 = 2 * lane;   // rows r0, r0+1
    __syncthreads();

    float* Hr = Ha; float* Hw = Hb;
    float* Xc = Xa; float* Xn = Xb;

    for (int t = 0; t < Tn; ++t) {
        // prefetch x for t+1 (hidden under GEMM)
        float4 xp[2];
        if (t < Tn - 1) {
            #pragma unroll
            for (int rep = 0; rep < 2; ++rep) {
                const int i = tid + rep * 512;
                const int row = i >> 4, kq = i & 15;
                xp[rep] = *(const float4*)&x[(size_t)((b0 + row) * Tn + t + 1) * 64 + 4 * kq];
            }
        }
        const float m0 = mval(mask, (b0 + r0) * Tn + t, mode);
        const float m1 = mval(mask, (b0 + r0 + 1) * Tn + t, mode);

        // accumulators: [row r][colpair cp]
        unsigned long long zac[2][2], rac[2][2], xhac[2][2], rhac[2][2];
        zac[0][0] = bzP0; zac[0][1] = bzP1; zac[1][0] = bzP0; zac[1][1] = bzP1;
        rac[0][0] = brP0; rac[0][1] = brP1; rac[1][0] = brP0; rac[1][1] = brP1;
        xhac[0][0] = bxP0; xhac[0][1] = bxP1; xhac[1][0] = bxP0; xhac[1][1] = bxP1;
        rhac[0][0] = bhP0; rhac[0][1] = bhP1; rhac[1][0] = bhP0; rhac[1][1] = bhP1;

        #pragma unroll 4
        for (int k = 0; k < 64; ++k) {
            const float2 h2 = *(const float2*)&Hr[k * 66 + r0];
            const float2 x2 = *(const float2*)&Xc[k * 66 + r0];
            const ulonglong2 uz = *(const ulonglong2*)&Us[k * 192 + c0];
            const ulonglong2 ur = *(const ulonglong2*)&Us[k * 192 + 64 + c0];
            const ulonglong2 uh = *(const ulonglong2*)&Us[k * 192 + 128 + c0];
            const ulonglong2 wz = *(const ulonglong2*)&Ws[k * 192 + c0];
            const ulonglong2 wr = *(const ulonglong2*)&Ws[k * 192 + 64 + c0];
            const ulonglong2 wh = *(const ulonglong2*)&Ws[k * 192 + 128 + c0];
            const unsigned long long h0 = dup2(h2.x), h1 = dup2(h2.y);
            const unsigned long long x0 = dup2(x2.x), x1 = dup2(x2.y);
            fma2(zac[0][0], h0, uz.x);  fma2(zac[0][1], h0, uz.y);
            fma2(zac[1][0], h1, uz.x);  fma2(zac[1][1], h1, uz.y);
            fma2(zac[0][0], x0, wz.x);  fma2(zac[0][1], x0, wz.y);
            fma2(zac[1][0], x1, wz.x);  fma2(zac[1][1], x1, wz.y);
            fma2(rac[0][0], h0, ur.x);  fma2(rac[0][1], h0, ur.y);
            fma2(rac[1][0], h1, ur.x);  fma2(rac[1][1], h1, ur.y);
            fma2(rac[0][0], x0, wr.x);  fma2(rac[0][1], x0, wr.y);
            fma2(rac[1][0], x1, wr.x);  fma2(rac[1][1], x1, wr.y);
            fma2(rhac[0][0], h0, uh.x); fma2(rhac[0][1], h0, uh.y);
            fma2(rhac[1][0], h1, uh.x); fma2(rhac[1][1], h1, uh.y);
            fma2(xhac[0][0], x0, wh.x); fma2(xhac[0][1], x0, wh.y);
            fma2(xhac[1][0], x1, wh.x); fma2(xhac[1][1], x1, wh.y);
        }

        // gates + state update
        #pragma unroll
        for (int r = 0; r < 2; ++r) {
            const float m = r ? m1 : m0;
            float zv[4], rv[4], xh[4], rh[4];
            { float2 v;
              v = unp(zac[r][0]);  zv[0] = v.x; zv[1] = v.y;
              v = unp(zac[r][1]);  zv[2] = v.x; zv[3] = v.y;
              v = unp(rac[r][0]);  rv[0] = v.x; rv[1] = v.y;
              v = unp(rac[r][1]);  rv[2] = v.x; rv[3] = v.y;
              v = unp(xhac[r][0]); xh[0] = v.x; xh[1] = v.y;
              v = unp(xhac[r][1]); xh[2] = v.x; xh[3] = v.y;
              v = unp(rhac[r][0]); rh[0] = v.x; rh[1] = v.y;
              v = unp(rhac[r][1]); rh[2] = v.x; rh[3] = v.y; }
            float hn[4];
            #pragma unroll
            for (int jj = 0; jj < 4; ++jj) {
                const float ho = Hr[(c0 + jj) * 66 + r0 + r];
                const float z = sigf(zv[jj]);
                const float rr_ = sigf(rv[jj]);
                const float hh = tanhf_(xh[jj] + rr_ * rh[jj]);
                const float v = z * ho + (1.0f - z) * hh;
                hn[jj] = (m != 0.0f) ? v : ho;
                Hw[(c0 + jj) * 66 + r0 + r] = hn[jj];
            }
            float4 o; o.x = hn[0]; o.y = hn[1]; o.z = hn[2]; o.w = hn[3];
            *(float4*)&y[(size_t)((b0 + r0 + r) * Tn + t) * 64 + c0] = o;
        }

        // stage X for t+1
        if (t < Tn - 1) {
            #pragma unroll
            for (int rep = 0; rep < 2; ++rep) {
                const int i = tid + rep * 512;
                const int row = i >> 4, kq = i & 15;
                Xn[(4 * kq + 0) * 66 + row] = xp[rep].x;
                Xn[(4 * kq + 1) * 66 + row] = xp[rep].y;
                Xn[(4 * kq + 2) * 66 + row] = xp[rep].z;
                Xn[(4 * kq + 3) * 66 + row] = xp[rep].w;
            }
        }
        __syncthreads();
        { float* tp = Hr; Hr = Hw; Hw = tp; }
        { float* tp = Xc; Xc = Xn; Xn = tp; }
    }
}

// -------- MLP via tf32 mma.sync: persistent CTAs, fragment-order smem --------
#define O_W1F  0
#define O_W2F  16384
#define O_AFG  24576
#define O_AFX  28672
#define O_AFN  32768
#define O_H1F  36864
#define O_PP   45056
#define O_PN   45312
#define O_B1   45568
#define O_B2   45696
#define O_W3   45760
#define O_RED  45824
#define O_TSK  45888

__device__ __forceinline__ int afidx(int row, int k) {
    const int mt = row >> 4, ks = k >> 3;
    const int lane = ((row & 7) << 2) | (k & 3);
    const int slot = ((row >> 3) & 1) + (((k >> 2) & 1) << 1);
    return (((mt << 3) + ks) << 5 | lane) * 4 + slot;
}
__device__ __forceinline__ int h1idx(int row, int j) {
    const int mt = row >> 4, ks = j >> 3;
    const int lane = ((row & 7) << 2) | (j & 3);
    const int slot = ((row >> 3) & 1) + (((j >> 2) & 1) << 1);
    return (((mt << 4) + ks) << 5 | lane) * 4 + slot;
}

__global__ void __launch_bounds__(512, 1) mlp_k(
    const float* __restrict__ ub, const float* __restrict__ nub,
    const float* __restrict__ w1, const float* __restrict__ b1,
    const float* __restrict__ w2, const float* __restrict__ b2,
    const float* __restrict__ w3, const float* __restrict__ b3,
    const float* __restrict__ y)
{
    extern __shared__ float sm[];
    unsigned* W1F = (unsigned*)(sm + O_W1F);
    unsigned* W2F = (unsigned*)(sm + O_W2F);
    unsigned* AFG = (unsigned*)(sm + O_AFG);
    unsigned* AFX = (unsigned*)(sm + O_AFX);
    unsigned* AFN = (unsigned*)(sm + O_AFN);
    unsigned* H1F = (unsigned*)(sm + O_H1F);
    float* partP = sm + O_PP;
    float* partN = sm + O_PN;
    float* b1s = sm + O_B1;
    float* b2s = sm + O_B2;
    float* w3s = sm + O_W3;
    float* red = sm + O_RED;
    int*   tsk = (int*)(sm + O_TSK);

    const int tid = threadIdx.x, lane = tid & 31, w = tid >> 5;
    const int g = lane >> 2, tig = lane & 3;
    const int mt = w & 3, ng = w >> 2;

    for (int idx = tid; idx < 16 * 16 * 32; idx += 512) {
        const int l = idx & 31, nt = (idx >> 5) & 15, ks = idx >> 9;
        const int gg = l >> 2, tg = l & 3;
        W1F[idx * 2]     = tf32c(w1[(ks * 8 + tg) * 128 + nt * 8 + gg]);
        W1F[idx * 2 + 1] = tf32c(w1[(ks * 8 + tg + 4) * 128 + nt * 8 + gg]);
    }
    for (int idx = tid; idx < 16 * 8 * 32; idx += 512) {
        const int l = idx & 31, nt = (idx >> 5) & 7, ks = idx >> 8;
        const int gg = l >> 2, tg = l & 3;
        W2F[idx * 2]     = tf32c(w2[(ks * 8 + tg) * 64 + nt * 8 + gg]);
        W2F[idx * 2 + 1] = tf32c(w2[(ks * 8 + tg + 4) * 64 + nt * 8 + gg]);
    }
    if (tid < 128) b1s[tid] = b1[tid];
    if (tid >= 128 && tid < 192) b2s[tid - 128] = b2[tid - 128];
    if (tid >= 192 && tid < 256) w3s[tid - 192] = w3[tid - 192];

    const float b3v = b3[0];
    const float loge = logf(1e-7f);
    const float log1me = logf(1.0f - 1e-7f);
    const int nm = g_nm;
    const int ntiles = (nm + 63) >> 6;
    float accL = 0.0f;

    for (int tile = blockIdx.x; tile < ntiles; tile += NMLP_CTAS) {
        __syncthreads();
        if (tid < 64) tsk[tid] = g_tasks[tile * 64 + tid];
        __syncthreads();

        for (int i = tid; i < 1024; i += 512) {
            const int row = i >> 4, kq = i & 15, k0 = kq * 4;
            int tk = tsk[row]; if (tk < 0) tk = 0;
            const int b = tk >> 6, tt = tk & 63;
            const size_t prow = (size_t)(b * 40 + 1 + tt) * 64 + k0;
            const size_t nrow = (size_t)(b * 39 + tt) * 64 + k0;
            float4 v;
            v = *(const float4*)&y[prow];
            AFG[afidx(row, k0)]     = tf32c(v.x);
            AFG[afidx(row, k0 + 1)] = tf32c(v.y);
            AFG[afidx(row, k0 + 2)] = tf32c(v.z);
            AFG[afidx(row, k0 + 3)] = tf32c(v.w);
            v = *(const float4*)&ub[prow];
            AFX[afidx(row, k0)]     = tf32c(v.x);
            AFX[afidx(row, k0 + 1)] = tf32c(v.y);
            AFX[afidx(row, k0 + 2)] = tf32c(v.z);
            AFX[afidx(row, k0 + 3)] = tf32c(v.w);
            v = *(const float4*)&nub[nrow];
            AFN[afidx(row, k0)]     = tf32c(v.x);
            AFN[afidx(row, k0 + 1)] = tf32c(v.y);
            AFN[afidx(row, k0 + 2)] = tf32c(v.z);
            AFN[afidx(row, k0 + 3)] = tf32c(v.w);
        }
        __syncthreads();

        float cg[4][4] = {};
        #pragma unroll
        for (int ks = 0; ks < 8; ++ks) {
            const uint4 a = ((const uint4*)AFG)[(mt * 8 + ks) * 32 + lane];
            #pragma unroll
            for (int i = 0; i < 4; ++i) {
                const int nt = ng * 4 + i;
                const uint2 b = ((const uint2*)W1F)[(ks * 16 + nt) * 32 + lane];
                mma_tf32(cg[i], a, b);
            }
        }

        // positive branch
        {
            float cp[4][4];
            #pragma unroll
            for (int i = 0; i < 4; ++i)
                #pragma unroll
                for (int q = 0; q < 4; ++q) cp[i][q] = cg[i][q];
            #pragma unroll
            for (int ks = 0; ks < 8; ++ks) {
                const uint4 a = ((const uint4*)AFX)[(mt * 8 + ks) * 32 + lane];
                #pragma unroll
                for (int i = 0; i < 4; ++i) {
                    const int nt = ng * 4 + i;
                    const uint2 b = ((const uint2*)W1F)[((ks + 8) * 16 + nt) * 32 + lane];
                    mma_tf32(cp[i], a, b);
                }
            }
            const int row1 = mt * 16 + g;
            #pragma unroll
            for (int i = 0; i < 4; ++i) {
                const int j0 = (ng * 4 + i) * 8 + 2 * tig;
                H1F[h1idx(row1, j0)]         = tf32c(fmaxf(cp[i][0] + b1s[j0], 0.0f));
                H1F[h1idx(row1, j0 + 1)]     = tf32c(fmaxf(cp[i][1] + b1s[j0 + 1], 0.0f));
                H1F[h1idx(row1 + 8, j0)]     = tf32c(fmaxf(cp[i][2] + b1s[j0], 0.0f));
                H1F[h1idx(row1 + 8, j0 + 1)] = tf32c(fmaxf(cp[i][3] + b1s[j0 + 1], 0.0f));
            }
        }
        __syncthreads();
        {
            float c2[2][4] = {};
            #pragma unroll
            for (int ks = 0; ks < 16; ++ks) {
                const uint4 a = ((const uint4*)H1F)[(mt * 16 + ks) * 32 + lane];
                #pragma unroll
                for (int i = 0; i < 2; ++i) {
                    const int nt = ng * 2 + i;
                    const uint2 b = ((const uint2*)W2F)[(ks * 8 + nt) * 32 + lane];
                    mma_tf32(c2[i], a, b);
                }
            }
            float s1 = 0.0f, s2 = 0.0f;
            #pragma unroll
            for (int i = 0; i < 2; ++i) {
                const int j0 = (ng * 2 + i) * 8 + 2 * tig;
                s1 += fmaxf(c2[i][0] + b2s[j0], 0.0f) * w3s[j0]
                    + fmaxf(c2[i][1] + b2s[j0 + 1], 0.0f) * w3s[j0 + 1];
                s2 += fmaxf(c2[i][2] + b2s[j0], 0.0f) * w3s[j0]
                    + fmaxf(c2[i][3] + b2s[j0 + 1], 0.0f) * w3s[j0 + 1];
            }
            s1 += __shfl_xor_sync(0xffffffffu, s1, 1);
            s1 += __shfl_xor_sync(0xffffffffu, s1, 2);
            s2 += __shfl_xor_sync(0xffffffffu, s2, 1);
            s2 += __shfl_xor_sync(0xffffffffu, s2, 2);
            if (tig == 0) {
                partP[ng * 64 + mt * 16 + g] = s1;
                partP[ng * 64 + mt * 16 + 8 + g] = s2;
            }
        }
        __syncthreads();

        // negative branch
        {
            float cn[4][4];
            #pragma unroll
            for (int i = 0; i < 4; ++i)
                #pragma unroll
                for (int q = 0; q < 4; ++q) cn[i][q] = cg[i][q];
            #pragma unroll
            for (int ks = 0; ks < 8; ++ks) {
                const uint4 a = ((const uint4*)AFN)[(mt * 8 + ks) * 32 + lane];
                #pragma unroll
                for (int i = 0; i < 4; ++i) {
                    const int nt = ng * 4 + i;
                    const uint2 b = ((const uint2*)W1F)[((ks + 8) * 16 + nt) * 32 + lane];
                    mma_tf32(cn[i], a, b);
                }
            }
            const int row1 = mt * 16 + g;
            #pragma unroll
            for (int i = 0; i < 4; ++i) {
                const int j0 = (ng * 4 + i) * 8 + 2 * tig;
                H1F[h1idx(row1, j0)]         = tf32c(fmaxf(cn[i][0] + b1s[j0], 0.0f));
                H1F[h1idx(row1, j0 + 1)]     = tf32c(fmaxf(cn[i][1] + b1s[j0 + 1], 0.0f));
                H1F[h1idx(row1 + 8, j0)]     = tf32c(fmaxf(cn[i][2] + b1s[j0], 0.0f));
                H1F[h1idx(row1 + 8, j0 + 1)] = tf32c(fmaxf(cn[i][3] + b1s[j0 + 1], 0.0f));
            }
        }
        __syncthreads();
        {
            float c2[2][4] = {};
            #pragma unroll
            for (int ks = 0; ks < 16; ++ks) {
                const uint4 a = ((const uint4*)H1F)[(mt * 16 + ks) * 32 + lane];
                #pragma unroll
                for (int i = 0; i < 2; ++i) {
                    const int nt = ng * 2 + i;
                    const uint2 b = ((const uint2*)W2F)[(ks * 8 + nt) * 32 + lane];
                    mma_tf32(c2[i], a, b);
                }
            }
            float s1 = 0.0f, s2 = 0.0f;
            #pragma unroll
            for (int i = 0; i < 2; ++i) {
                const int j0 = (ng * 2 + i) * 8 + 2 * tig;
                s1 += fmaxf(c2[i][0] + b2s[j0], 0.0f) * w3s[j0]
                    + fmaxf(c2[i][1] + b2s[j0 + 1], 0.0f) * w3s[j0 + 1];
                s2 += fmaxf(c2[i][2] + b2s[j0], 0.0f) * w3s[j0]
                    + fmaxf(c2[i][3] + b2s[j0 + 1], 0.0f) * w3s[j0 + 1];
            }
            s1 += __shfl_xor_sync(0xffffffffu, s1, 1);
            s1 += __shfl_xor_sync(0xffffffffu, s1, 2);
            s2 += __shfl_xor_sync(0xffffffffu, s2, 1);
            s2 += __shfl_xor_sync(0xffffffffu, s2, 2);
            if (tig == 0) {
                partN[ng * 64 + mt * 16 + g] = s1;
                partN[ng * 64 + mt * 16 + 8 + g] = s2;
            }
        }
        __syncthreads();

        if (tid < 64 && tsk[tid] >= 0) {
            const float lp_ = partP[tid] + partP[64 + tid] + partP[128 + tid]
                            + partP[192 + tid] + b3v;
            const float ln_ = partN[tid] + partN[64 + tid] + partN[128 + tid]
                            + partN[192 + tid] + b3v;
            const float p  = sigf(lp_);
            const float pn = sigf(ln_);
            accL += -(p  * log1me + (1.0f - p)  * loge)
                    - (pn * loge  + (1.0f - pn) * log1me);
        }
    }

    __syncthreads();
    if (tid < 64) red[tid] = 0.0f;
    __syncthreads();
    for (int grp = 0; grp < 8; ++grp) {
        if ((tid >> 6) == grp) red[tid & 63] += accL;
        __syncthreads();
    }
    if (tid == 0) {
        float L = 0.0f;
        for (int i = 0; i < 64; ++i) L += red[i];
        g_partials[blockIdx.x] = L;
    }
}

// -------- deterministic final reduction --------
__global__ void fin_k(float* __restrict__ out, int out_size) {
    __shared__ float s[256];
    float L = 0.0f;
    for (int i = threadIdx.x; i < NMLP_CTAS; i += 256) L += g_partials[i];
    s[threadIdx.x] = L; __syncthreads();
    for (int off = 128; off; off >>= 1) {
        if (threadIdx.x < off) s[threadIdx.x] += s[threadIdx.x + off];
        __syncthreads();
    }
    if (threadIdx.x == 0) {
        const float cnt = fmaxf((float)g_nm, 1.0f);
        out[out_size - 1] = s[0] / (2.0f * cnt);
    }
}

extern "C" void kernel_launch(void* const* d_in, const int* in_sizes, int n_in,
                              void* d_out, int out_size) {
    const float* ub    = (const float*)d_in[0];
    const void*  mask  = d_in[1];
    const float* nub   = (const float*)d_in[2];
    const void*  nmask = d_in[3];
    const float* W     = (const float*)d_in[4];
    const float* U     = (const float*)d_in[5];
    const float* bias  = (const float*)d_in[6];
    const float* w1    = (const float*)d_in[7];
    const float* b1    = (const float*)d_in[8];
    const float* w2    = (const float*)d_in[9];
    const float* b2    = (const float*)d_in[10];
    const float* w3    = (const float*)d_in[11];
    const float* b3    = (const float*)d_in[12];
    float* y = (float*)d_out;

    cudaFuncSetAttribute(gruf_k, cudaFuncAttributeMaxDynamicSharedMemorySize, FUSED_SMEM);
    cudaFuncSetAttribute(mlp_k,  cudaFuncAttributeMaxDynamicSharedMemorySize, MLP_SMEM);

    detect_k<<<1, 256>>>((const int*)mask);
    cnt_k<<<32, 256>>>(nmask);
    off_k<<<1, 256>>>();
    fill_k<<<32, 256>>>(nmask);
    gruf_k<<<128, 512, FUSED_SMEM>>>(ub, mask, W, U, bias, y);
    mlp_k<<<NMLP_CTAS, 512, MLP_SMEM>>>(ub, nub, w1, b1, w2, b2, w3, b3, y);
    fin_k<<<1, 256>>>(y, out_size);
}

// round 11
// speedup vs baseline: 2.9404x; 1.0025x over previous
#include <cuda_runtime.h>
#include <cuda_bf16.h>
#include <math.h>

// Problem constants
#define Bn 8192
#define Tn 40
#define En 64
#define NTILES 4992               // ceil(8192*39/64)
#define NMLP_CTAS 148

#define GRUF_SMEM ((24576 + 2*8704 + 256)*4)   // 168960 B
#define MLP_SMEM  (45952*4)                    // 183808 B

// -------- device scratch (no allocations allowed) --------
__device__ int   g_maskMode;              // 0=u8, 1=int32, 2=float32
__device__ float g_partials[NMLP_CTAS];
__device__ int   g_tasks[NTILES * 64];
__device__ int   g_cnt[Bn];
__device__ int   g_off[Bn];
__device__ int   g_ord[Bn];               // rows sorted by length desc (stable)
__device__ int   g_nm;

__device__ __forceinline__ float mval(const void* m, int idx, int mode) {
    if (mode == 1) return ((const int*)m)[idx] ? 1.0f : 0.0f;
    if (mode == 2) return ((const float*)m)[idx];
    return ((const unsigned char*)m)[idx] ? 1.0f : 0.0f;
}
__device__ __forceinline__ float sigf(float v) { return 1.0f / (1.0f + __expf(-v)); }
__device__ __forceinline__ float tanhf_(float v) {
    return 1.0f - 2.0f / (__expf(2.0f * v) + 1.0f);
}

// packed f32x2 helpers
__device__ __forceinline__ unsigned long long dup2(float x) {
    unsigned long long r; unsigned u = __float_as_uint(x);
    asm("mov.b64 %0, {%1, %1};" : "=l"(r) : "r"(u));
    return r;
}
__device__ __forceinline__ void fma2(unsigned long long& d,
                                     unsigned long long a, unsigned long long b) {
    asm("fma.rn.f32x2 %0, %1, %2, %0;" : "+l"(d) : "l"(a), "l"(b));
}
__device__ __forceinline__ float2 unp(unsigned long long v) {
    unsigned lo, hi;
    asm("mov.b64 {%0, %1}, %2;" : "=r"(lo), "=r"(hi) : "l"(v));
    return make_float2(__uint_as_float(lo), __uint_as_float(hi));
}

// tf32 helpers
__device__ __forceinline__ unsigned tf32c(float x) {
    unsigned r; asm("cvt.rna.tf32.f32 %0, %1;" : "=r"(r) : "f"(x)); return r;
}
__device__ __forceinline__ void mma_tf32(float c[4], const uint4& a, const uint2& b) {
    asm("mma.sync.aligned.m16n8k8.row.col.f32.tf32.tf32.f32 "
        "{%0,%1,%2,%3}, {%4,%5,%6,%7}, {%8,%9}, {%0,%1,%2,%3};"
        : "+f"(c[0]), "+f"(c[1]), "+f"(c[2]), "+f"(c[3])
        : "r"(a.x), "r"(a.y), "r"(a.z), "r"(a.w), "r"(b.x), "r"(b.y));
}

// -------- mask dtype probe (reads only within smallest candidate buffer) --------
__global__ void detect_k(const int* __restrict__ m32) {
    __shared__ int sB, sF;
    if (threadIdx.x == 0) { sB = 1; sF = 1; }
    __syncthreads();
    int okB = 1, okF = 1;
    for (int i = threadIdx.x; i < 2560; i += blockDim.x) {
        int v = m32[i];
        okB = okB && (v == 0 || v == 1);
        okF = okF && (v == 0 || v == 0x3F800000);
    }
    atomicAnd(&sB, okB);
    atomicAnd(&sF, okF);
    __syncthreads();
    if (threadIdx.x == 0) g_maskMode = sB ? 1 : (sF ? 2 : 0);
}

// -------- per-row valid-count of neg mask (= len-1, since mask is a prefix) --------
__global__ void cnt_k(const void* __restrict__ nmask) {
    const int b = blockIdx.x * 256 + threadIdx.x;
    const int mode = g_maskMode;
    int c = 0;
    #pragma unroll
    for (int tt = 0; tt < 39; ++tt)
        c += (mval(nmask, b * 39 + tt, mode) != 0.0f);
    g_cnt[b] = c;
}

// -------- exclusive offsets + tail padding (deterministic) --------
__global__ void off_k() {
    __shared__ int ssum[256];
    const int tid = threadIdx.x;
    int c[32]; int tot = 0;
    #pragma unroll
    for (int r = 0; r < 32; ++r) { c[r] = g_cnt[tid * 32 + r]; tot += c[r]; }
    ssum[tid] = tot; __syncthreads();
    for (int off = 1; off < 256; off <<= 1) {
        int v = (tid >= off) ? ssum[tid - off] : 0;
        __syncthreads();
        ssum[tid] += v;
        __syncthreads();
    }
    int base = ssum[tid] - tot;
    #pragma unroll
    for (int r = 0; r < 32; ++r) { g_off[tid * 32 + r] = base; base += c[r]; }
    const int total = ssum[255];
    const int padded = ((total + 63) >> 6) << 6;
    for (int i = total + tid; i < padded; i += 256) g_tasks[i] = -1;
    if (tid == 0) g_nm = total;
}

// -------- fill compacted task list --------
__global__ void fill_k(const void* __restrict__ nmask) {
    const int b = blockIdx.x * 256 + threadIdx.x;
    const int mode = g_maskMode;
    int off = g_off[b];
    #pragma unroll
    for (int tt = 0; tt < 39; ++tt)
        if (mval(nmask, b * 39 + tt, mode) != 0.0f) g_tasks[off++] = (b << 6) | tt;
}

// -------- stable counting sort of rows by length, descending --------
__global__ void sort_k() {
    __shared__ int hist[41];
    __shared__ int offs[41];
    const int tid = threadIdx.x;
    if (tid < 41) hist[tid] = 0;
    __syncthreads();
    for (int b = tid; b < Bn; b += 1024) {
        int len = g_cnt[b] + 1;           // len in 1..40
        if (len < 1) len = 1; if (len > 40) len = 40;
        atomicAdd(&hist[len], 1);
    }
    __syncthreads();
    if (tid == 0) {
        int run = 0;
        for (int L = 40; L >= 1; --L) { offs[L] = run; run += hist[L]; }
    }
    __syncthreads();
    const int wid = tid >> 5, lane = tid & 31;
    #pragma unroll
    for (int r = 0; r < 2; ++r) {
        const int L = 40 - (wid + 32 * r);
        if (L < 1) continue;
        int pos = offs[L];
        for (int base = 0; base < Bn; base += 32) {
            const int b = base + lane;
            int len = g_cnt[b] + 1;
            if (len < 1) len = 1; if (len > 40) len = 40;
            const bool p = (len == L);
            const unsigned m = __ballot_sync(0xffffffffu, p);
            if (p) g_ord[pos + __popc(m & ((1u << lane) - 1u))] = b;
            pos += __popc(m);
        }
    }
}

// -------- fused xproj + GRU, length-sorted, two independent 256-thread groups --------
// 128 CTAs x 512 threads. Group g (warps 8g..8g+7) processes sorted chunk
// (g==0 ? bid : 255-bid) of 32 rows; pairing balances lenA+lenB ~= const.
// Within a group: lane owns 1 row; warp w owns cols 8w..8w+7 of each gate
// section (weight LDS.128 are full-warp broadcasts). Groups sync with named
// barriers (1 and 2) so the short group exits early and frees the fma pipe.
// Steps t >= maxlen(chunk) only carry h: y written from registers, no GEMM.
__global__ void __launch_bounds__(512, 1) gruf_k(
    const float* __restrict__ x, const void* __restrict__ mask,
    const float* __restrict__ W, const float* __restrict__ U,
    const float* __restrict__ bias, float* __restrict__ y)
{
    extern __shared__ float sm[];
    float* Ws  = sm;               // 12288  [k][192]
    float* Us  = sm + 12288;       // 12288
    float* grp = sm + 24576;       // 2 x 8704: per-group H(2x2176) + X(2x2176)
    float* zbS = sm + 24576 + 17408;   // 64: bias_z_in + bias_z_rec
    float* rbS = zbS + 64;             // 64
    float* xbS = rbS + 64;             // 64
    float* hbS = xbS + 64;             // 64

    const int tid = threadIdx.x;
    const int g   = tid >> 8;          // group 0/1
    const int gt  = tid & 255;
    const int w   = gt >> 5, l = gt & 31;
    const int c0  = 8 * w;

    for (int i = tid; i < 3072; i += 512) {
        ((float4*)Ws)[i] = ((const float4*)W)[i];
        ((float4*)Us)[i] = ((const float4*)U)[i];
    }
    for (int i = tid; i < 17408; i += 512) grp[i] = 0.0f;
    if (tid < 64) {
        zbS[tid] = bias[tid] + bias[192 + tid];
        rbS[tid] = bias[64 + tid] + bias[256 + tid];
        xbS[tid] = bias[128 + tid];
        hbS[tid] = bias[320 + tid];
    }
    __syncthreads();   // last CTA-wide barrier before group divergence

    float* base = grp + g * 8704;
    float* Ha = base;            // [64][34]
    float* Hb = base + 2176;
    float* Xa = base + 4352;
    float* Xb = base + 6528;

    const int ck  = g ? (255 - (int)blockIdx.x) : (int)blockIdx.x;
    const int row = g_ord[ck * 32 + l];
    int len = g_cnt[row] + 1;
    if (len < 1) len = 1; if (len > 40) len = 40;
    int ml = len;
    #pragma unroll
    for (int o = 16; o; o >>= 1) ml = max(ml, __shfl_xor_sync(0xffffffffu, ml, o));

    const int mode = g_maskMode;
    const int bar = g + 1;

    // stage X for t=0: this thread loads its row's quads w and w+8
    #pragma unroll
    for (int rep = 0; rep < 2; ++rep) {
        const int kq = w + 8 * rep;
        const float4 v = *(const float4*)&x[(size_t)(row * Tn + 0) * 64 + 4 * kq];
        Xa[(4 * kq + 0) * 34 + l] = v.x;
        Xa[(4 * kq + 1) * 34 + l] = v.y;
        Xa[(4 * kq + 2) * 34 + l] = v.z;
        Xa[(4 * kq + 3) * 34 + l] = v.w;
    }
    asm volatile("bar.sync %0, %1;" :: "r"(bar), "r"(256) : "memory");

    float* Hr = Ha; float* Hw = Hb;
    float* Xc = Xa; float* Xn = Xb;
    float hn[8];
    #pragma unroll
    for (int j = 0; j < 8; ++j) hn[j] = 0.0f;

    for (int t = 0; t < ml; ++t) {
        // prefetch x for t+1
        float4 xp0, xp1;
        const bool pf = (t + 1 < ml);
        if (pf) {
            xp0 = *(const float4*)&x[(size_t)(row * Tn + t + 1) * 64 + 4 * w];
            xp1 = *(const float4*)&x[(size_t)(row * Tn + t + 1) * 64 + 4 * (w + 8)];
        }
        const float m = mval(mask, row * Tn + t, mode);

        unsigned long long zac[4], rac[4], xha[4], rha[4];
        #pragma unroll
        for (int q = 0; q < 4; ++q) {
            zac[q] = *(const unsigned long long*)&zbS[c0 + 2 * q];
            rac[q] = *(const unsigned long long*)&rbS[c0 + 2 * q];
            xha[q] = *(const unsigned long long*)&xbS[c0 + 2 * q];
            rha[q] = *(const unsigned long long*)&hbS[c0 + 2 * q];
        }

        #pragma unroll 4
        for (int k = 0; k < 64; ++k) {
            const float hv = Hr[k * 34 + l];
            const float xv = Xc[k * 34 + l];
            const unsigned long long hd = dup2(hv), xd = dup2(xv);
            const ulonglong2 uzA = *(const ulonglong2*)&Us[k * 192 + c0];
            const ulonglong2 uzB = *(const ulonglong2*)&Us[k * 192 + c0 + 4];
            const ulonglong2 urA = *(const ulonglong2*)&Us[k * 192 + 64 + c0];
            const ulonglong2 urB = *(const ulonglong2*)&Us[k * 192 + 64 + c0 + 4];
            const ulonglong2 uhA = *(const ulonglong2*)&Us[k * 192 + 128 + c0];
            const ulonglong2 uhB = *(const ulonglong2*)&Us[k * 192 + 128 + c0 + 4];
            const ulonglong2 wzA = *(const ulonglong2*)&Ws[k * 192 + c0];
            const ulonglong2 wzB = *(const ulonglong2*)&Ws[k * 192 + c0 + 4];
            const ulonglong2 wrA = *(const ulonglong2*)&Ws[k * 192 + 64 + c0];
            const ulonglong2 wrB = *(const ulonglong2*)&Ws[k * 192 + 64 + c0 + 4];
            const ulonglong2 whA = *(const ulonglong2*)&Ws[k * 192 + 128 + c0];
            const ulonglong2 whB = *(const ulonglong2*)&Ws[k * 192 + 128 + c0 + 4];
            fma2(zac[0], hd, uzA.x); fma2(zac[1], hd, uzA.y);
            fma2(zac[2], hd, uzB.x); fma2(zac[3], hd, uzB.y);
            fma2(zac[0], xd, wzA.x); fma2(zac[1], xd, wzA.y);
            fma2(zac[2], xd, wzB.x); fma2(zac[3], xd, wzB.y);
            fma2(rac[0], hd, urA.x); fma2(rac[1], hd, urA.y);
            fma2(rac[2], hd, urB.x); fma2(rac[3], hd, urB.y);
            fma2(rac[0], xd, wrA.x); fma2(rac[1], xd, wrA.y);
            fma2(rac[2], xd, wrB.x); fma2(rac[3], xd, wrB.y);
            fma2(rha[0], hd, uhA.x); fma2(rha[1], hd, uhA.y);
            fma2(rha[2], hd, uhB.x); fma2(rha[3], hd, uhB.y);
            fma2(xha[0], xd, whA.x); fma2(xha[1], xd, whA.y);
            fma2(xha[2], xd, whB.x); fma2(xha[3], xd, whB.y);
        }

        // gates + state update (cols c0..c0+7 of this thread's row)
        #pragma unroll
        for (int q = 0; q < 4; ++q) {
            const float2 zz = unp(zac[q]);
            const float2 rr = unp(rac[q]);
            const float2 xx = unp(xha[q]);
            const float2 hh = unp(rha[q]);
            #pragma unroll
            for (int s = 0; s < 2; ++s) {
                const int col = c0 + 2 * q + s;
                const float ho = Hr[col * 34 + l];
                const float zval = s ? zz.y : zz.x;
                const float rval = s ? rr.y : rr.x;
                const float xval = s ? xx.y : xx.x;
                const float hval = s ? hh.y : hh.x;
                const float z  = sigf(zval);
                const float rg = sigf(rval);
                const float hc = tanhf_(xval + rg * hval);
                const float v  = z * ho + (1.0f - z) * hc;
                const float nv = (m != 0.0f) ? v : ho;
                hn[2 * q + s] = nv;
                Hw[col * 34 + l] = nv;
            }
        }
        { float4 o; o.x = hn[0]; o.y = hn[1]; o.z = hn[2]; o.w = hn[3];
          *(float4*)&y[(size_t)(row * Tn + t) * 64 + c0] = o;
          o.x = hn[4]; o.y = hn[5]; o.z = hn[6]; o.w = hn[7];
          *(float4*)&y[(size_t)(row * Tn + t) * 64 + c0 + 4] = o; }

        if (pf) {
            Xn[(4 * w + 0) * 34 + l] = xp0.x;
            Xn[(4 * w + 1) * 34 + l] = xp0.y;
            Xn[(4 * w + 2) * 34 + l] = xp0.z;
            Xn[(4 * w + 3) * 34 + l] = xp0.w;
            Xn[(4 * (w + 8) + 0) * 34 + l] = xp1.x;
            Xn[(4 * (w + 8) + 1) * 34 + l] = xp1.y;
            Xn[(4 * (w + 8) + 2) * 34 + l] = xp1.z;
            Xn[(4 * (w + 8) + 3) * 34 + l] = xp1.w;
        }
        asm volatile("bar.sync %0, %1;" :: "r"(bar), "r"(256) : "memory");
        { float* tp = Hr; Hr = Hw; Hw = tp; }
        { float* tp = Xc; Xc = Xn; Xn = tp; }
    }

    // carried tail: y[t] = h_final for t >= maxlen
    for (int t = ml; t < Tn; ++t) {
        float4 o; o.x = hn[0]; o.y = hn[1]; o.z = hn[2]; o.w = hn[3];
        *(float4*)&y[(size_t)(row * Tn + t) * 64 + c0] = o;
        o.x = hn[4]; o.y = hn[5]; o.z = hn[6]; o.w = hn[7];
        *(float4*)&y[(size_t)(row * Tn + t) * 64 + c0 + 4] = o;
    }
}

// -------- MLP via tf32 mma.sync: persistent CTAs, fragment-order smem --------
#define O_W1F  0
#define O_W2F  16384
#define O_AFG  24576
#define O_AFX  28672
#define O_AFN  32768
#define O_H1F  36864
#define O_PP   45056
#define O_PN   45312
#define O_B1   45568
#define O_B2   45696
#define O_W3   45760
#define O_RED  45824
#define O_TSK  45888

__device__ __forceinline__ int afidx(int row, int k) {
    const int mt = row >> 4, ks = k >> 3;
    const int lane = ((row & 7) << 2) | (k & 3);
    const int slot = ((row >> 3) & 1) + (((k >> 2) & 1) << 1);
    return (((mt << 3) + ks) << 5 | lane) * 4 + slot;
}
__device__ __forceinline__ int h1idx(int row, int j) {
    const int mt = row >> 4, ks = j >> 3;
    const int lane = ((row & 7) << 2) | (j & 3);
    const int slot = ((row >> 3) & 1) + (((j >> 2) & 1) << 1);
    return (((mt << 4) + ks) << 5 | lane) * 4 + slot;
}

__global__ void __launch_bounds__(512, 1) mlp_k(
    const float* __restrict__ ub, const float* __restrict__ nub,
    const float* __restrict__ w1, const float* __restrict__ b1,
    const float* __restrict__ w2, const float* __restrict__ b2,
    const float* __restrict__ w3, const float* __restrict__ b3,
    const float* __restrict__ y)
{
    extern __shared__ float sm[];
    unsigned* W1F = (unsigned*)(sm + O_W1F);
    unsigned* W2F = (unsigned*)(sm + O_W2F);
    unsigned* AFG = (unsigned*)(sm + O_AFG);
    unsigned* AFX = (unsigned*)(sm + O_AFX);
    unsigned* AFN = (unsigned*)(sm + O_AFN);
    unsigned* H1F = (unsigned*)(sm + O_H1F);
    float* partP = sm + O_PP;
    float* partN = sm + O_PN;
    float* b1s = sm + O_B1;
    float* b2s = sm + O_B2;
    float* w3s = sm + O_W3;
    float* red = sm + O_RED;
    int*   tsk = (int*)(sm + O_TSK);

    const int tid = threadIdx.x, lane = tid & 31, w = tid >> 5;
    const int g = lane >> 2, tig = lane & 3;
    const int mt = w & 3, ng = w >> 2;

    for (int idx = tid; idx < 16 * 16 * 32; idx += 512) {
        const int l = idx & 31, nt = (idx >> 5) & 15, ks = idx >> 9;
        const int gg = l >> 2, tg = l & 3;
        W1F[idx * 2]     = tf32c(w1[(ks * 8 + tg) * 128 + nt * 8 + gg]);
        W1F[idx * 2 + 1] = tf32c(w1[(ks * 8 + tg + 4) * 128 + nt * 8 + gg]);
    }
    for (int idx = tid; idx < 16 * 8 * 32; idx += 512) {
        const int l = idx & 31, nt = (idx >> 5) & 7, ks = idx >> 8;
        const int gg = l >> 2, tg = l & 3;
        W2F[idx * 2]     = tf32c(w2[(ks * 8 + tg) * 64 + nt * 8 + gg]);
        W2F[idx * 2 + 1] = tf32c(w2[(ks * 8 + tg + 4) * 64 + nt * 8 + gg]);
    }
    if (tid < 128) b1s[tid] = b1[tid];
    if (tid >= 128 && tid < 192) b2s[tid - 128] = b2[tid - 128];
    if (tid >= 192 && tid < 256) w3s[tid - 192] = w3[tid - 192];

    const float b3v = b3[0];
    const float loge = logf(1e-7f);
    const float log1me = logf(1.0f - 1e-7f);
    const int nm = g_nm;
    const int ntiles = (nm + 63) >> 6;
    float accL = 0.0f;

    for (int tile = blockIdx.x; tile < ntiles; tile += NMLP_CTAS) {
        __syncthreads();
        if (tid < 64) tsk[tid] = g_tasks[tile * 64 + tid];
        __syncthreads();

        for (int i = tid; i < 1024; i += 512) {
            const int row = i >> 4, kq = i & 15, k0 = kq * 4;
            int tk = tsk[row]; if (tk < 0) tk = 0;
            const int b = tk >> 6, tt = tk & 63;
            const size_t prow = (size_t)(b * 40 + 1 + tt) * 64 + k0;
            const size_t nrow = (size_t)(b * 39 + tt) * 64 + k0;
            float4 v;
            v = *(const float4*)&y[prow];
            AFG[afidx(row, k0)]     = tf32c(v.x);
            AFG[afidx(row, k0 + 1)] = tf32c(v.y);
            AFG[afidx(row, k0 + 2)] = tf32c(v.z);
            AFG[afidx(row, k0 + 3)] = tf32c(v.w);
            v = *(const float4*)&ub[prow];
            AFX[afidx(row, k0)]     = tf32c(v.x);
            AFX[afidx(row, k0 + 1)] = tf32c(v.y);
            AFX[afidx(row, k0 + 2)] = tf32c(v.z);
            AFX[afidx(row, k0 + 3)] = tf32c(v.w);
            v = *(const float4*)&nub[nrow];
            AFN[afidx(row, k0)]     = tf32c(v.x);
            AFN[afidx(row, k0 + 1)] = tf32c(v.y);
            AFN[afidx(row, k0 + 2)] = tf32c(v.z);
            AFN[afidx(row, k0 + 3)] = tf32c(v.w);
        }
        __syncthreads();

        float cg[4][4] = {};
        #pragma unroll
        for (int ks = 0; ks < 8; ++ks) {
            const uint4 a = ((const uint4*)AFG)[(mt * 8 + ks) * 32 + lane];
            #pragma unroll
            for (int i = 0; i < 4; ++i) {
                const int nt = ng * 4 + i;
                const uint2 b = ((const uint2*)W1F)[(ks * 16 + nt) * 32 + lane];
                mma_tf32(cg[i], a, b);
            }
        }

        // positive branch
        {
            float cp[4][4];
            #pragma unroll
            for (int i = 0; i < 4; ++i)
                #pragma unroll
                for (int q = 0; q < 4; ++q) cp[i][q] = cg[i][q];
            #pragma unroll
            for (int ks = 0; ks < 8; ++ks) {
                const uint4 a = ((const uint4*)AFX)[(mt * 8 + ks) * 32 + lane];
                #pragma unroll
                for (int i = 0; i < 4; ++i) {
                    const int nt = ng * 4 + i;
                    const uint2 b = ((const uint2*)W1F)[((ks + 8) * 16 + nt) * 32 + lane];
                    mma_tf32(cp[i], a, b);
                }
            }
            const int row1 = mt * 16 + g;
            #pragma unroll
            for (int i = 0; i < 4; ++i) {
                const int j0 = (ng * 4 + i) * 8 + 2 * tig;
                H1F[h1idx(row1, j0)]         = tf32c(fmaxf(cp[i][0] + b1s[j0], 0.0f));
                H1F[h1idx(row1, j0 + 1)]     = tf32c(fmaxf(cp[i][1] + b1s[j0 + 1], 0.0f));
                H1F[h1idx(row1 + 8, j0)]     = tf32c(fmaxf(cp[i][2] + b1s[j0], 0.0f));
                H1F[h1idx(row1 + 8, j0 + 1)] = tf32c(fmaxf(cp[i][3] + b1s[j0 + 1], 0.0f));
            }
        }
        __syncthreads();
        {
            float c2[2][4] = {};
            #pragma unroll
            for (int ks = 0; ks < 16; ++ks) {
                const uint4 a = ((const uint4*)H1F)[(mt * 16 + ks) * 32 + lane];
                #pragma unroll
                for (int i = 0; i < 2; ++i) {
                    const int nt = ng * 2 + i;
                    const uint2 b = ((const uint2*)W2F)[(ks * 8 + nt) * 32 + lane];
                    mma_tf32(c2[i], a, b);
                }
            }
            float s1 = 0.0f, s2 = 0.0f;
            #pragma unroll
            for (int i = 0; i < 2; ++i) {
                const int j0 = (ng * 2 + i) * 8 + 2 * tig;
                s1 += fmaxf(c2[i][0] + b2s[j0], 0.0f) * w3s[j0]
                    + fmaxf(c2[i][1] + b2s[j0 + 1], 0.0f) * w3s[j0 + 1];
                s2 += fmaxf(c2[i][2] + b2s[j0], 0.0f) * w3s[j0]
                    + fmaxf(c2[i][3] + b2s[j0 + 1], 0.0f) * w3s[j0 + 1];
            }
            s1 += __shfl_xor_sync(0xffffffffu, s1, 1);
            s1 += __shfl_xor_sync(0xffffffffu, s1, 2);
            s2 += __shfl_xor_sync(0xffffffffu, s2, 1);
            s2 += __shfl_xor_sync(0xffffffffu, s2, 2);
            if (tig == 0) {
                partP[ng * 64 + mt * 16 + g] = s1;
                partP[ng * 64 + mt * 16 + 8 + g] = s2;
            }
        }
        __syncthreads();

        // negative branch
        {
            float cn[4][4];
            #pragma unroll
            for (int i = 0; i < 4; ++i)
                #pragma unroll
                for (int q = 0; q < 4; ++q) cn[i][q] = cg[i][q];
            #pragma unroll
            for (int ks = 0; ks < 8; ++ks) {
                const uint4 a = ((const uint4*)AFN)[(mt * 8 + ks) * 32 + lane];
                #pragma unroll
                for (int i = 0; i < 4; ++i) {
                    const int nt = ng * 4 + i;
                    const uint2 b = ((const uint2*)W1F)[((ks + 8) * 16 + nt) * 32 + lane];
                    mma_tf32(cn[i], a, b);
                }
            }
            const int row1 = mt * 16 + g;
            #pragma unroll
            for (int i = 0; i < 4; ++i) {
                const int j0 = (ng * 4 + i) * 8 + 2 * tig;
                H1F[h1idx(row1, j0)]         = tf32c(fmaxf(cn[i][0] + b1s[j0], 0.0f));
                H1F[h1idx(row1, j0 + 1)]     = tf32c(fmaxf(cn[i][1] + b1s[j0 + 1], 0.0f));
                H1F[h1idx(row1 + 8, j0)]     = tf32c(fmaxf(cn[i][2] + b1s[j0], 0.0f));
                H1F[h1idx(row1 + 8, j0 + 1)] = tf32c(fmaxf(cn[i][3] + b1s[j0 + 1], 0.0f));
            }
        }
        __syncthreads();
        {
            float c2[2][4] = {};
            #pragma unroll
            for (int ks = 0; ks < 16; ++ks) {
                const uint4 a = ((const uint4*)H1F)[(mt * 16 + ks) * 32 + lane];
                #pragma unroll
                for (int i = 0; i < 2; ++i) {
                    const int nt = ng * 2 + i;
                    const uint2 b = ((const uint2*)W2F)[(ks * 8 + nt) * 32 + lane];
                    mma_tf32(c2[i], a, b);
                }
            }
            float s1 = 0.0f, s2 = 0.0f;
            #pragma unroll
            for (int i = 0; i < 2; ++i) {
                const int j0 = (ng * 2 + i) * 8 + 2 * tig;
                s1 += fmaxf(c2[i][0] + b2s[j0], 0.0f) * w3s[j0]
                    + fmaxf(c2[i][1] + b2s[j0 + 1], 0.0f) * w3s[j0 + 1];
                s2 += fmaxf(c2[i][2] + b2s[j0], 0.0f) * w3s[j0]
                    + fmaxf(c2[i][3] + b2s[j0 + 1], 0.0f) * w3s[j0 + 1];
            }
            s1 += __shfl_xor_sync(0xffffffffu, s1, 1);
            s1 += __shfl_xor_sync(0xffffffffu, s1, 2);
            s2 += __shfl_xor_sync(0xffffffffu, s2, 1);
            s2 += __shfl_xor_sync(0xffffffffu, s2, 2);
            if (tig == 0) {
                partN[ng * 64 + mt * 16 + g] = s1;
                partN[ng * 64 + mt * 16 + 8 + g] = s2;
            }
        }
        __syncthreads();

        if (tid < 64 && tsk[tid] >= 0) {
            const float lp_ = partP[tid] + partP[64 + tid] + partP[128 + tid]
                            + partP[192 + tid] + b3v;
            const float ln_ = partN[tid] + partN[64 + tid] + partN[128 + tid]
                            + partN[192 + tid] + b3v;
            const float p  = sigf(lp_);
            const float pn = sigf(ln_);
            accL += -(p  * log1me + (1.0f - p)  * loge)
                    - (pn * loge  + (1.0f - pn) * log1me);
        }
    }

    __syncthreads();
    if (tid < 64) red[tid] = 0.0f;
    __syncthreads();
    for (int grp = 0; grp < 8; ++grp) {
        if ((tid >> 6) == grp) red[tid & 63] += accL;
        __syncthreads();
    }
    if (tid == 0) {
        float L = 0.0f;
        for (int i = 0; i < 64; ++i) L += red[i];
        g_partials[blockIdx.x] = L;
    }
}

// -------- deterministic final reduction --------
__global__ void fin_k(float* __restrict__ out, int out_size) {
    __shared__ float s[256];
    float L = 0.0f;
    for (int i = threadIdx.x; i < NMLP_CTAS; i += 256) L += g_partials[i];
    s[threadIdx.x] = L; __syncthreads();
    for (int off = 128; off; off >>= 1) {
        if (threadIdx.x < off) s[threadIdx.x] += s[threadIdx.x + off];
        __syncthreads();
    }
    if (threadIdx.x == 0) {
        const float cnt = fmaxf((float)g_nm, 1.0f);
        out[out_size - 1] = s[0] / (2.0f * cnt);
    }
}

extern "C" void kernel_launch(void* const* d_in, const int* in_sizes, int n_in,
                              void* d_out, int out_size) {
    const float* ub    = (const float*)d_in[0];
    const void*  mask  = d_in[1];
    const float* nub   = (const float*)d_in[2];
    const void*  nmask = d_in[3];
    const float* W     = (const float*)d_in[4];
    const float* U     = (const float*)d_in[5];
    const float* bias  = (const float*)d_in[6];
    const float* w1    = (const float*)d_in[7];
    const float* b1    = (const float*)d_in[8];
    const float* w2    = (const float*)d_in[9];
    const float* b2    = (const float*)d_in[10];
    const float* w3    = (const float*)d_in[11];
    const float* b3    = (const float*)d_in[12];
    float* y = (float*)d_out;

    cudaFuncSetAttribute(gruf_k, cudaFuncAttributeMaxDynamicSharedMemorySize, GRUF_SMEM);
    cudaFuncSetAttribute(mlp_k,  cudaFuncAttributeMaxDynamicSharedMemorySize, MLP_SMEM);

    detect_k<<<1, 256>>>((const int*)mask);
    cnt_k<<<32, 256>>>(nmask);
    off_k<<<1, 256>>>();
    fill_k<<<32, 256>>>(nmask);
    sort_k<<<1, 1024>>>();
    gruf_k<<<128, 512, GRUF_SMEM>>>(ub, mask, W, U, bias, y);
    mlp_k<<<NMLP_CTAS, 512, MLP_SMEM>>>(ub, nub, w1, b1, w2, b2, w3, b3, y);
    fin_k<<<1, 256>>>(y, out_size);
}